// round 5
// baseline (speedup 1.0000x reference)
#include <cuda_runtime.h>

#define HH 512
#define WW 512
#define BATCH 2
#define CMID 64
#define HWSZ (HH*WW)

typedef unsigned long long ull;

// Packed f32x2 helpers (Blackwell sm_100a, PTX ISA 8.6)
__device__ __forceinline__ ull pk2(float lo, float hi) {
    ull r;
    asm("mov.b64 %0, {%1, %2};" : "=l"(r)
        : "r"(__float_as_uint(lo)), "r"(__float_as_uint(hi)));
    return r;
}
__device__ __forceinline__ void fma2(ull& d, ull a, ull b) {
    asm("fma.rn.f32x2 %0, %1, %2, %0;" : "+l"(d) : "l"(a), "l"(b));
}
__device__ __forceinline__ float2 up2(ull p) {
    unsigned lo, hi;
    asm("mov.b64 {%0, %1}, %2;" : "=r"(lo), "=r"(hi) : "l"(p));
    return make_float2(__uint_as_float(lo), __uint_as_float(hi));
}

// Persistent scratch (device globals: allocation-free, graph-capturable)
__device__ float g_bufA[BATCH*CMID*HWSZ];
__device__ float g_bufB[BATCH*CMID*HWSZ];
__device__ float g_bufC[BATCH*CMID*HWSZ];
__device__ float g_filt[BATCH*30*HWSZ];
__device__ float g_fh[BATCH*3*HWSZ];

// ---------------------------------------------------------------------------
// conv 7x7, Cin=6 -> 64, pad 3, ReLU. Packed f32x2 math.
// Block: 256 thr = 8 cout-groups x 32 pixel-slots; tile 8H x 16W; 4 px/thread
// (2 packed pairs).
// ---------------------------------------------------------------------------
__global__ __launch_bounds__(256) void conv7x7_kernel(
    const float* __restrict__ in, const float* __restrict__ wt,
    float* __restrict__ out)
{
    __shared__ __align__(16) float  s_in[6][14][24];  // rows h0-3..h0+10, cols w0-3..w0+18
    __shared__ __align__(16) float2 s_w[64][7][8];    // duplicated {w,w}, row pad->8

    const int tid  = threadIdx.x;
    const int cg   = tid >> 5;
    const int slot = tid & 31;
    const int pr   = slot >> 2;
    const int pc4  = (slot & 3) * 4;
    const int h0   = blockIdx.y * 8;
    const int w0   = blockIdx.x * 16;
    const int b    = blockIdx.z;

    for (int i = tid; i < 6*14*22; i += 256) {
        int ci = i / (14*22);
        int r  = (i / 22) % 14;
        int c  = i % 22;
        int gh = h0 - 3 + r;
        int gw = w0 - 3 + c;
        float v = 0.f;
        if (gh >= 0 && gh < HH && gw >= 0 && gw < WW)
            v = in[((b*6 + ci)*HH + gh)*WW + gw];
        s_in[ci][r][c] = v;
    }

    ull acc[8][2];
    #pragma unroll
    for (int c = 0; c < 8; c++) { acc[c][0] = 0ull; acc[c][1] = 0ull; }

    for (int cin = 0; cin < 6; cin++) {
        __syncthreads();
        for (int i = tid; i < 64*49; i += 256) {
            int co = i / 49, k = i % 49;
            float v = wt[(co*6 + cin)*49 + k];
            s_w[co][k/7][k%7] = make_float2(v, v);
        }
        __syncthreads();
        for (int ky = 0; ky < 7; ky++) {
            float xr[10];
            const float* rp = &s_in[cin][pr + ky][pc4];
            float4 v0 = *(const float4*)rp;
            float4 v1 = *(const float4*)(rp + 4);
            float2 v2 = *(const float2*)(rp + 8);
            xr[0]=v0.x; xr[1]=v0.y; xr[2]=v0.z; xr[3]=v0.w;
            xr[4]=v1.x; xr[5]=v1.y; xr[6]=v1.z; xr[7]=v1.w;
            xr[8]=v2.x; xr[9]=v2.y;
            ull xp[9];
            #pragma unroll
            for (int j = 0; j < 9; j++) xp[j] = pk2(xr[j], xr[j+1]);
            #pragma unroll
            for (int c = 0; c < 8; c++) {
                const ull* wp = (const ull*)&s_w[cg*8 + c][ky][0];
                ulonglong2 wa = *(const ulonglong2*)wp;        // w0,w1
                ulonglong2 wb = *(const ulonglong2*)(wp + 2);  // w2,w3
                ulonglong2 wc = *(const ulonglong2*)(wp + 4);  // w4,w5
                ull        wd = wp[6];                          // w6
                fma2(acc[c][0], xp[0], wa.x); fma2(acc[c][1], xp[2], wa.x);
                fma2(acc[c][0], xp[1], wa.y); fma2(acc[c][1], xp[3], wa.y);
                fma2(acc[c][0], xp[2], wb.x); fma2(acc[c][1], xp[4], wb.x);
                fma2(acc[c][0], xp[3], wb.y); fma2(acc[c][1], xp[5], wb.y);
                fma2(acc[c][0], xp[4], wc.x); fma2(acc[c][1], xp[6], wc.x);
                fma2(acc[c][0], xp[5], wc.y); fma2(acc[c][1], xp[7], wc.y);
                fma2(acc[c][0], xp[6], wd);   fma2(acc[c][1], xp[8], wd);
            }
        }
    }

    const int h = h0 + pr;
    #pragma unroll
    for (int c = 0; c < 8; c++) {
        int co = cg*8 + c;
        float2 f0 = up2(acc[c][0]);
        float2 f1 = up2(acc[c][1]);
        float4 v;
        v.x = fmaxf(f0.x, 0.f);
        v.y = fmaxf(f0.y, 0.f);
        v.z = fmaxf(f1.x, 0.f);
        v.w = fmaxf(f1.y, 0.f);
        *(float4*)&out[((b*64 + co)*HH + h)*WW + w0 + pc4] = v;
    }
}

// ---------------------------------------------------------------------------
// conv 3x3, Cin=64 -> COUT, pad 1, optional BN / ReLU / skip-add.
// Packed f32x2: NC couts x 2 pixel-pairs per thread.
// ---------------------------------------------------------------------------
template<int NC, int COUT, bool BN, bool RELU, bool SKIP>
__global__ __launch_bounds__(256) void conv3x3_kernel(
    const float* __restrict__ in, const float* __restrict__ wt,
    const float* __restrict__ bng, const float* __restrict__ bnb,
    const float* __restrict__ bnm, const float* __restrict__ bnv,
    const float* __restrict__ skip, float* __restrict__ out)
{
    constexpr int CP = 8 * NC;          // couts covered per block (>= COUT)
    __shared__ __align__(16) float  s_in[8][10][20];  // 8 cin x 10 rows x 18 cols (pad 20)
    __shared__ __align__(16) float2 s_w[8][CP][10];   // duplicated {w,w}, 9 taps pad->10

    const int tid  = threadIdx.x;
    const int cg   = tid >> 5;
    const int slot = tid & 31;
    const int pr   = slot >> 2;
    const int pc4  = (slot & 3) * 4;
    const int h0   = blockIdx.y * 8;
    const int w0   = blockIdx.x * 16;
    const int b    = blockIdx.z;

    ull acc[NC][2];
    #pragma unroll
    for (int c = 0; c < NC; c++) { acc[c][0] = 0ull; acc[c][1] = 0ull; }

    for (int cc = 0; cc < 8; cc++) {
        const int cin0 = cc * 8;
        __syncthreads();
        for (int i = tid; i < 8*10*18; i += 256) {
            int ci = i / 180;
            int r  = (i / 18) % 10;
            int c  = i % 18;
            int gh = h0 - 1 + r;
            int gw = w0 - 1 + c;
            float v = 0.f;
            if (gh >= 0 && gh < HH && gw >= 0 && gw < WW)
                v = in[((b*64 + cin0 + ci)*HH + gh)*WW + gw];
            s_in[ci][r][c] = v;
        }
        for (int i = tid; i < CP*72; i += 256) {
            int co = i / 72;
            int r  = i % 72;          // (ci, k) contiguous in global weights
            float v = 0.f;
            if (CP == COUT || co < COUT)
                v = wt[(co*64 + cin0)*9 + r];
            s_w[r/9][co][r%9] = make_float2(v, v);
        }
        __syncthreads();

        for (int ci = 0; ci < 8; ci++) {
            float xr[3][6];
            #pragma unroll
            for (int dr = 0; dr < 3; dr++) {
                const float* rp = &s_in[ci][pr + dr][pc4];
                float4 a  = *(const float4*)rp;
                float2 b2 = *(const float2*)(rp + 4);
                xr[dr][0]=a.x; xr[dr][1]=a.y; xr[dr][2]=a.z; xr[dr][3]=a.w;
                xr[dr][4]=b2.x; xr[dr][5]=b2.y;
            }
            ull xp[3][5];
            #pragma unroll
            for (int dr = 0; dr < 3; dr++)
                #pragma unroll
                for (int j = 0; j < 5; j++)
                    xp[dr][j] = pk2(xr[dr][j], xr[dr][j+1]);
            #pragma unroll
            for (int c = 0; c < NC; c++) {
                const ull* wp = (const ull*)&s_w[ci][cg*NC + c][0];
                ulonglong2 wa = *(const ulonglong2*)wp;        // w0,w1
                ulonglong2 wb = *(const ulonglong2*)(wp + 2);  // w2,w3
                ulonglong2 wc = *(const ulonglong2*)(wp + 4);  // w4,w5
                ulonglong2 wd = *(const ulonglong2*)(wp + 6);  // w6,w7
                ull        we = wp[8];                          // w8
                fma2(acc[c][0], xp[0][0], wa.x); fma2(acc[c][1], xp[0][2], wa.x);
                fma2(acc[c][0], xp[0][1], wa.y); fma2(acc[c][1], xp[0][3], wa.y);
                fma2(acc[c][0], xp[0][2], wb.x); fma2(acc[c][1], xp[0][4], wb.x);
                fma2(acc[c][0], xp[1][0], wb.y); fma2(acc[c][1], xp[1][2], wb.y);
                fma2(acc[c][0], xp[1][1], wc.x); fma2(acc[c][1], xp[1][3], wc.x);
                fma2(acc[c][0], xp[1][2], wc.y); fma2(acc[c][1], xp[1][4], wc.y);
                fma2(acc[c][0], xp[2][0], wd.x); fma2(acc[c][1], xp[2][2], wd.x);
                fma2(acc[c][0], xp[2][1], wd.y); fma2(acc[c][1], xp[2][3], wd.y);
                fma2(acc[c][0], xp[2][2], we);   fma2(acc[c][1], xp[2][4], we);
            }
        }
    }

    const int h = h0 + pr;
    #pragma unroll
    for (int c = 0; c < NC; c++) {
        const int co = cg*NC + c;
        if (CP != COUT && co >= COUT) continue;
        float2 f0 = up2(acc[c][0]);
        float2 f1 = up2(acc[c][1]);
        float vals[4] = {f0.x, f0.y, f1.x, f1.y};
        if (BN) {
            float sc = bng[co] * rsqrtf(bnv[co] + 1e-5f);
            float sh = bnb[co] - bnm[co] * sc;
            #pragma unroll
            for (int p = 0; p < 4; p++) vals[p] = vals[p]*sc + sh;
        }
        if (RELU) {
            #pragma unroll
            for (int p = 0; p < 4; p++) vals[p] = fmaxf(vals[p], 0.f);
        }
        const int oidx = ((b*COUT + co)*HH + h)*WW + w0 + pc4;
        if (SKIP) {
            float4 sk = *(const float4*)&skip[oidx];
            vals[0] += sk.x; vals[1] += sk.y; vals[2] += sk.z; vals[3] += sk.w;
        }
        float4 v = {vals[0], vals[1], vals[2], vals[3]};
        *(float4*)&out[oidx] = v;
    }
}

// ---------------------------------------------------------------------------
// Adaptive filtering. Channel c of the 30-ch conv output maps to
// (color = c/10, tap j = c%10): j<5 -> vertical weights, j>=5 -> horizontal.
// ---------------------------------------------------------------------------
__global__ __launch_bounds__(256) void filt_h_kernel(
    const float* __restrict__ filt, const float* __restrict__ base,
    float* __restrict__ fh)
{
    int idx = blockIdx.x * 256 + threadIdx.x;   // [b][ch][h][w]
    int w  = idx & 511;
    int h  = (idx >> 9) & 511;
    int bc = idx >> 18;          // b*3 + ch
    int ch = bc % 3;
    int b  = bc / 3;

    const float* lp = filt + ((b*30 + ch*10)*HH + h)*WW + w;
    float l[5];
    #pragma unroll
    for (int i = 0; i < 5; i++) l[i] = lp[i*HWSZ];
    float m = fmaxf(fmaxf(fmaxf(l[0], l[1]), fmaxf(l[2], l[3])), l[4]);
    float e[5], s = 0.f;
    #pragma unroll
    for (int i = 0; i < 5; i++) { e[i] = __expf(l[i] - m); s += e[i]; }
    float inv = 1.f / s;

    const float* bp = base + bc*HWSZ + w;
    float r = 0.f;
    #pragma unroll
    for (int i = 0; i < 5; i++) {
        int hh2 = h - 2 + i;
        float bv = (hh2 >= 0 && hh2 < HH) ? bp[hh2*WW] : 0.f;
        r += bv * e[i] * inv;
    }
    fh[idx] = r;
}

__global__ __launch_bounds__(256) void filt_w_kernel(
    const float* __restrict__ filt, const float* __restrict__ fh,
    float* __restrict__ out)
{
    int idx = blockIdx.x * 256 + threadIdx.x;
    int w  = idx & 511;
    int h  = (idx >> 9) & 511;
    int bc = idx >> 18;
    int ch = bc % 3;
    int b  = bc / 3;

    const float* lp = filt + ((b*30 + ch*10 + 5)*HH + h)*WW + w;
    float l[5];
    #pragma unroll
    for (int i = 0; i < 5; i++) l[i] = lp[i*HWSZ];
    float m = fmaxf(fmaxf(fmaxf(l[0], l[1]), fmaxf(l[2], l[3])), l[4]);
    float e[5], s = 0.f;
    #pragma unroll
    for (int i = 0; i < 5; i++) { e[i] = __expf(l[i] - m); s += e[i]; }
    float inv = 1.f / s;

    const float* fp = fh + (bc*HH + h)*WW;
    float r = 0.f;
    #pragma unroll
    for (int i = 0; i < 5; i++) {
        int ww2 = w - 2 + i;
        float fv = (ww2 >= 0 && ww2 < WW) ? fp[ww2] : 0.f;
        r += fv * e[i] * inv;
    }
    out[idx] = r;
}

// ---------------------------------------------------------------------------
extern "C" void kernel_launch(void* const* d_in, const int* in_sizes, int n_in,
                              void* d_out, int out_size)
{
    const float* fm     = (const float*)d_in[0];
    const float* base   = (const float*)d_in[1];
    const float* wfirst = (const float*)d_in[2];
    const float* kbw1   = (const float*)d_in[3];
    const float* kbg1   = (const float*)d_in[4];
    const float* kbb1   = (const float*)d_in[5];
    const float* kbm1   = (const float*)d_in[6];
    const float* kbv1   = (const float*)d_in[7];
    const float* kbw2   = (const float*)d_in[8];
    const float* kbg2   = (const float*)d_in[9];
    const float* kbb2   = (const float*)d_in[10];
    const float* kbm2   = (const float*)d_in[11];
    const float* kbv2   = (const float*)d_in[12];
    const float* wlast  = (const float*)d_in[13];
    float* out = (float*)d_out;

    float *A, *Bf, *Cbuf, *F, *FHp;
    cudaGetSymbolAddress((void**)&A,    g_bufA);
    cudaGetSymbolAddress((void**)&Bf,   g_bufB);
    cudaGetSymbolAddress((void**)&Cbuf, g_bufC);
    cudaGetSymbolAddress((void**)&F,    g_filt);
    cudaGetSymbolAddress((void**)&FHp,  g_fh);

    dim3 grid(WW/16, HH/8, BATCH), blk(256);

    conv7x7_kernel<<<grid, blk>>>(fm, wfirst, A);

    float* cur   = A;
    float* spare = Cbuf;
    for (int i = 0; i < 4; i++) {
        conv3x3_kernel<8,64,true,true,false><<<grid, blk>>>(
            cur, kbw1 + i*36864,
            kbg1 + i*64, kbb1 + i*64, kbm1 + i*64, kbv1 + i*64,
            nullptr, Bf);
        conv3x3_kernel<8,64,true,true,true><<<grid, blk>>>(
            Bf, kbw2 + i*36864,
            kbg2 + i*64, kbb2 + i*64, kbm2 + i*64, kbv2 + i*64,
            cur, spare);
        float* t = cur; cur = spare; spare = t;
    }

    conv3x3_kernel<4,30,false,false,false><<<grid, blk>>>(
        cur, wlast, nullptr, nullptr, nullptr, nullptr, nullptr, F);

    int npix = BATCH*3*HWSZ;
    filt_h_kernel<<<npix/256, 256>>>(F, base, FHp);
    filt_w_kernel<<<npix/256, 256>>>(F, FHp, out);
}

// round 7
// speedup vs baseline: 2.2788x; 2.2788x over previous
#include <cuda_runtime.h>
#include <cuda_bf16.h>
#include <cstdint>

#define HH 512
#define WW 512
#define BATCH 2
#define HWSZ (HH*WW)

// ===========================================================================
// Warp-MMA helpers (family-compatible: ldmatrix sm_75+, bf16 mma.sync sm_80+)
// ===========================================================================
__device__ __forceinline__ uint32_t smem_u32(const void* p) {
    uint32_t a;
    asm("{ .reg .u64 t; cvta.to.shared.u64 t, %1; cvt.u32.u64 %0, t; }"
        : "=r"(a) : "l"(p));
    return a;
}
__device__ __forceinline__ void ldsm_x4(uint32_t* r, uint32_t addr) {
    asm volatile("ldmatrix.sync.aligned.m8n8.x4.shared.b16 {%0,%1,%2,%3}, [%4];"
        : "=r"(r[0]), "=r"(r[1]), "=r"(r[2]), "=r"(r[3]) : "r"(addr));
}
__device__ __forceinline__ void ldsm_x4_t(uint32_t* r, uint32_t addr) {
    asm volatile("ldmatrix.sync.aligned.m8n8.x4.trans.shared.b16 {%0,%1,%2,%3}, [%4];"
        : "=r"(r[0]), "=r"(r[1]), "=r"(r[2]), "=r"(r[3]) : "r"(addr));
}
__device__ __forceinline__ void mma_bf16(float* d, const uint32_t* a,
                                         uint32_t b0, uint32_t b1) {
    asm volatile("mma.sync.aligned.m16n8k16.row.col.f32.bf16.bf16.f32 "
        "{%0,%1,%2,%3}, {%4,%5,%6,%7}, {%8,%9}, {%0,%1,%2,%3};"
        : "+f"(d[0]), "+f"(d[1]), "+f"(d[2]), "+f"(d[3])
        : "r"(a[0]), "r"(a[1]), "r"(a[2]), "r"(a[3]), "r"(b0), "r"(b1));
}
// SW128-style XOR swizzle for 128B-row tiles (B smem)
__device__ __forceinline__ uint32_t swzB(uint32_t off) {
    return off ^ ((off >> 3) & 0x70);
}
// swizzle for 256B-row tiles (A smem): chunk' = (c&8) | ((c^row)&7)
__device__ __forceinline__ uint32_t swzA(int row, int kbyte) {
    int c = kbyte >> 4;
    int cs = (c & 8) | ((c ^ row) & 7);
    return (uint32_t)(row * 256 + (cs << 4));
}

// ===========================================================================
// Persistent scratch
// ===========================================================================
__device__ float g_bufA[(size_t)BATCH*64*HWSZ];     // fp32 NCHW (final block out)
__device__ float g_filt[(size_t)BATCH*30*HWSZ];
__device__ float g_fh[(size_t)BATCH*3*HWSZ];
// NHWC bf16 activation pairs [b][h][w][c]
__device__ __nv_bfloat16 g_P0h[(size_t)BATCH*HWSZ*64];
__device__ __nv_bfloat16 g_P0l[(size_t)BATCH*HWSZ*64];
__device__ __nv_bfloat16 g_P1h[(size_t)BATCH*HWSZ*64];
__device__ __nv_bfloat16 g_P1l[(size_t)BATCH*HWSZ*64];
__device__ __nv_bfloat16 g_P2h[(size_t)BATCH*HWSZ*64];
__device__ __nv_bfloat16 g_P2l[(size_t)BATCH*HWSZ*64];
// prepped weights [rc=4*2][tap=9][k=192][cout=64] bf16; k: [wh|wh|wl] over cin
__device__ __nv_bfloat16 g_Bg[(size_t)4*2*9*192*64];

// ===========================================================================
// Weight prep
// ===========================================================================
__global__ void prep_w_kernel(const float* __restrict__ w1, const float* __restrict__ w2,
                              __nv_bfloat16* __restrict__ Bg)
{
    int idx = blockIdx.x * 256 + threadIdx.x;
    if (idx >= 4*2*9*192*64) return;
    int co  = idx & 63;
    int k   = (idx >> 6) % 192;
    int tap = (idx >> 6) / 192 % 9;
    int rc  = idx / (192*64*9);
    int conv = rc & 1, r = rc >> 1;
    int cin = (k < 64) ? k : ((k < 128) ? k - 64 : k - 128);
    int ky = tap / 3, kx = tap % 3;
    const float* src = conv ? w2 : w1;
    float v = src[(((r*64 + co)*64 + cin)*3 + ky)*3 + kx];
    __nv_bfloat16 h = __float2bfloat16(v);
    if (k < 128) {
        Bg[idx] = h;
    } else {
        Bg[idx] = __float2bfloat16(v - __bfloat162float(h));
    }
}

// ===========================================================================
// conv 7x7, Cin=6 -> 64, pad 3, ReLU. Scalar fp32 (proven R1 body);
// outputs NHWC bf16 hi/lo.
// ===========================================================================
__global__ __launch_bounds__(256) void conv7x7_kernel(
    const float* __restrict__ in, const float* __restrict__ wt,
    __nv_bfloat16* __restrict__ out_hi, __nv_bfloat16* __restrict__ out_lo)
{
    __shared__ float s_in[6][14][24];
    __shared__ float s_w[64][7][8];

    const int tid  = threadIdx.x;
    const int cg   = tid >> 5;
    const int slot = tid & 31;
    const int pr   = slot >> 2;
    const int pc4  = (slot & 3) * 4;
    const int h0   = blockIdx.y * 8;
    const int w0   = blockIdx.x * 16;
    const int b    = blockIdx.z;

    for (int i = tid; i < 6*14*22; i += 256) {
        int ci = i / (14*22);
        int r  = (i / 22) % 14;
        int c  = i % 22;
        int gh = h0 - 3 + r;
        int gw = w0 - 3 + c;
        float v = 0.f;
        if (gh >= 0 && gh < HH && gw >= 0 && gw < WW)
            v = in[((b*6 + ci)*HH + gh)*WW + gw];
        s_in[ci][r][c] = v;
    }

    float acc[8][4];
    #pragma unroll
    for (int c = 0; c < 8; c++)
        #pragma unroll
        for (int p = 0; p < 4; p++) acc[c][p] = 0.f;

    for (int cin = 0; cin < 6; cin++) {
        __syncthreads();
        for (int i = tid; i < 64*49; i += 256) {
            int co = i / 49, k = i % 49;
            s_w[co][k/7][k%7] = wt[(co*6 + cin)*49 + k];
        }
        __syncthreads();
        #pragma unroll 1
        for (int ky = 0; ky < 7; ky++) {
            float xr[10];
            const float* rp = &s_in[cin][pr + ky][pc4];
            #pragma unroll
            for (int j = 0; j < 10; j++) xr[j] = rp[j];
            #pragma unroll
            for (int c = 0; c < 8; c++) {
                const float* wp = &s_w[cg*8 + c][ky][0];
                float wv[7];
                #pragma unroll
                for (int q = 0; q < 7; q++) wv[q] = wp[q];
                #pragma unroll
                for (int p = 0; p < 4; p++) {
                    float s = acc[c][p];
                    #pragma unroll
                    for (int q = 0; q < 7; q++) s += xr[p+q] * wv[q];
                    acc[c][p] = s;
                }
            }
        }
    }

    const int h = h0 + pr;
    #pragma unroll
    for (int p = 0; p < 4; p++) {
        int w = w0 + pc4 + p;
        size_t nb = ((size_t)((b*HH + h)*WW + w))*64 + cg*8;
        union { uint4 u; __nv_bfloat16 x[8]; } Uh, Ul;
        #pragma unroll
        for (int c = 0; c < 8; c++) {
            float v = fmaxf(acc[c][p], 0.f);
            __nv_bfloat16 hh = __float2bfloat16(v);
            Uh.x[c] = hh;
            Ul.x[c] = __float2bfloat16(v - __bfloat162float(hh));
        }
        *(uint4*)(out_hi + nb) = Uh.u;
        *(uint4*)(out_lo + nb) = Ul.u;
    }
}

// ===========================================================================
// Residual conv3x3 64->64 via mma.sync bf16 (3-term split, fp32 accum).
// CTA: 256 thr, tile M=128 pixels (one row) x N=64 couts. Warps: 4(M) x 2(N).
// A smem: 130px window x K=128 ([yh|yl]); B smem per tap: [k=192][cout 64].
// ===========================================================================
#define RES_SMEM (130*256 + 192*128 + 512)

template<bool SKIP, bool OUTF32>
__global__ __launch_bounds__(256) void res_conv_kernel(
    const __nv_bfloat16* __restrict__ in_hi, const __nv_bfloat16* __restrict__ in_lo,
    const __nv_bfloat16* __restrict__ Bg,
    const float* __restrict__ bng, const float* __restrict__ bnb,
    const float* __restrict__ bnm, const float* __restrict__ bnv,
    const __nv_bfloat16* __restrict__ sk_hi, const __nv_bfloat16* __restrict__ sk_lo,
    __nv_bfloat16* __restrict__ out_hi, __nv_bfloat16* __restrict__ out_lo,
    float* __restrict__ out_f32)
{
    extern __shared__ __align__(16) unsigned char dynsmem[];
    unsigned char* sA = dynsmem;                 // 130 rows x 256B
    unsigned char* sB = dynsmem + 130*256;       // 192 rows x 128B
    float* s_sc = (float*)(dynsmem + 130*256 + 192*128);
    float* s_sh = s_sc + 64;

    const int tid  = threadIdx.x;
    const int wid  = tid >> 5;
    const int lane = tid & 31;
    const int wm   = wid & 3;       // M-warp: pixels wm*32..+31
    const int wn   = wid >> 2;      // N-warp: couts wn*32..+31
    const int w0   = blockIdx.x * 128;
    const int h    = blockIdx.y;
    const int b    = blockIdx.z;

    const uint32_t aA = smem_u32(sA);
    const uint32_t aB = smem_u32(sB);

    if (tid < 64) {
        float sc = bng[tid] * rsqrtf(bnv[tid] + 1e-5f);
        s_sc[tid] = sc;
        s_sh[tid] = bnb[tid] - bnm[tid] * sc;
    }

    float d[2][4][4];
    #pragma unroll
    for (int mf = 0; mf < 2; mf++)
        #pragma unroll
        for (int nf = 0; nf < 4; nf++)
            #pragma unroll
            for (int q = 0; q < 4; q++) d[mf][nf][q] = 0.f;

    for (int ky = 0; ky < 3; ky++) {
        const int hs = h + ky - 1;
        const bool hok = (hs >= 0) && (hs < HH);
        __syncthreads();   // previous tap's ldmatrix reads complete
        // ---- load A window: 130 rows x (hi 128B | lo 128B) ----
        for (int idx = tid; idx < 260; idx += 256) {
            int r = idx % 130;
            int half = idx / 130;
            int ws = w0 - 1 + r;
            bool ok = hok && (ws >= 0) && (ws < WW);
            const uint4* src = (const uint4*)((half ? in_lo : in_hi)
                               + ((size_t)((b*HH + hs)*WW + ws))*64);
            #pragma unroll
            for (int j = 0; j < 8; j++) {
                uint4 v = ok ? src[j] : make_uint4(0u,0u,0u,0u);
                *(uint4*)(sA + swzA(r, half*128 + j*16)) = v;
            }
        }
        for (int kx = 0; kx < 3; kx++) {
            const int tap = ky*3 + kx;
            if (kx) __syncthreads();   // protect B reload
            // ---- load B tap: 192 rows x 128B ----
            {
                const __nv_bfloat16* bt = Bg + (size_t)tap*192*64;
                for (int idx = tid; idx < 1536; idx += 256) {
                    int kr = idx >> 3, c = idx & 7;
                    uint4 v = *(const uint4*)(bt + (size_t)kr*64 + c*8);
                    *(uint4*)(sB + swzB(kr*128 + c*16)) = v;
                }
            }
            __syncthreads();
            // ---- MMA: 12 k-slices (8 over [yh|yl]xwh, 4 over yh x wl) ----
            #pragma unroll 4
            for (int kidx = 0; kidx < 12; kidx++) {
                const int abyte = ((kidx < 8) ? kidx : (kidx - 8)) * 32 + (lane >> 4)*16;
                uint32_t a[2][4];
                #pragma unroll
                for (int mf = 0; mf < 2; mf++) {
                    int arow = wm*32 + mf*16 + (lane & 15) + kx;
                    ldsm_x4(a[mf], aA + swzA(arow, abyte));
                }
                uint32_t bf[2][4];
                const int krow = kidx*16 + (lane & 15);
                #pragma unroll
                for (int bq = 0; bq < 2; bq++) {
                    int colb = wn*64 + bq*32 + (lane >> 4)*16;
                    ldsm_x4_t(bf[bq], aB + swzB(krow*128 + colb));
                }
                #pragma unroll
                for (int mf = 0; mf < 2; mf++)
                    #pragma unroll
                    for (int nf = 0; nf < 4; nf++)
                        mma_bf16(d[mf][nf], a[mf],
                                 bf[nf >> 1][(nf & 1)*2], bf[nf >> 1][(nf & 1)*2 + 1]);
            }
        }
    }

    // ---- epilogue: BN + ReLU (+skip), emit bf16 pair NHWC or fp32 NCHW ----
    #pragma unroll
    for (int mf = 0; mf < 2; mf++) {
        #pragma unroll
        for (int rr = 0; rr < 2; rr++) {
            const int p = wm*32 + mf*16 + (lane >> 2) + rr*8;
            const int w = w0 + p;
            const size_t nbase = ((size_t)((b*HH + h)*WW + w))*64;
            #pragma unroll
            for (int nf = 0; nf < 4; nf++) {
                const int cout = wn*32 + nf*8 + (lane & 3)*2;
                float v0 = d[mf][nf][rr*2 + 0] * s_sc[cout]     + s_sh[cout];
                float v1 = d[mf][nf][rr*2 + 1] * s_sc[cout + 1] + s_sh[cout + 1];
                v0 = fmaxf(v0, 0.f);
                v1 = fmaxf(v1, 0.f);
                if (SKIP) {
                    uint32_t sh2 = *(const uint32_t*)(sk_hi + nbase + cout);
                    uint32_t sl2 = *(const uint32_t*)(sk_lo + nbase + cout);
                    v0 += __bfloat162float(__ushort_as_bfloat16((unsigned short)(sh2 & 0xFFFF)))
                        + __bfloat162float(__ushort_as_bfloat16((unsigned short)(sl2 & 0xFFFF)));
                    v1 += __bfloat162float(__ushort_as_bfloat16((unsigned short)(sh2 >> 16)))
                        + __bfloat162float(__ushort_as_bfloat16((unsigned short)(sl2 >> 16)));
                }
                if (OUTF32) {
                    out_f32[((size_t)(b*64 + cout    )*HH + h)*WW + w] = v0;
                    out_f32[((size_t)(b*64 + cout + 1)*HH + h)*WW + w] = v1;
                } else {
                    __nv_bfloat16 h0 = __float2bfloat16(v0);
                    __nv_bfloat16 h1 = __float2bfloat16(v1);
                    __nv_bfloat16 l0 = __float2bfloat16(v0 - __bfloat162float(h0));
                    __nv_bfloat16 l1 = __float2bfloat16(v1 - __bfloat162float(h1));
                    uint32_t ph = (uint32_t)__bfloat16_as_ushort(h0)
                                | ((uint32_t)__bfloat16_as_ushort(h1) << 16);
                    uint32_t pl = (uint32_t)__bfloat16_as_ushort(l0)
                                | ((uint32_t)__bfloat16_as_ushort(l1) << 16);
                    *(uint32_t*)(out_hi + nbase + cout) = ph;
                    *(uint32_t*)(out_lo + nbase + cout) = pl;
                }
            }
        }
    }
}

// ===========================================================================
// conv_last: scalar 3x3, 64 -> 30 (fp32 NCHW in/out)
// ===========================================================================
__global__ __launch_bounds__(256) void conv_last_kernel(
    const float* __restrict__ in, const float* __restrict__ wt,
    float* __restrict__ out)
{
    constexpr int NC = 4, COUT = 30, CP = 32;
    __shared__ float s_in[8][10][20];
    __shared__ float s_w[8][CP][12];

    const int tid  = threadIdx.x;
    const int cg   = tid >> 5;
    const int slot = tid & 31;
    const int pr   = slot >> 2;
    const int pc4  = (slot & 3) * 4;
    const int h0   = blockIdx.y * 8;
    const int w0   = blockIdx.x * 16;
    const int b    = blockIdx.z;

    float acc[NC][4];
    #pragma unroll
    for (int c = 0; c < NC; c++)
        #pragma unroll
        for (int p = 0; p < 4; p++) acc[c][p] = 0.f;

    for (int cc = 0; cc < 8; cc++) {
        const int cin0 = cc * 8;
        __syncthreads();
        for (int i = tid; i < 8*10*18; i += 256) {
            int ci = i / 180;
            int r  = (i / 18) % 10;
            int c  = i % 18;
            int gh = h0 - 1 + r;
            int gw = w0 - 1 + c;
            float v = 0.f;
            if (gh >= 0 && gh < HH && gw >= 0 && gw < WW)
                v = in[((size_t)(b*64 + cin0 + ci)*HH + gh)*WW + gw];
            s_in[ci][r][c] = v;
        }
        for (int i = tid; i < CP*72; i += 256) {
            int co = i / 72;
            int r  = i % 72;
            float v = 0.f;
            if (co < COUT) v = wt[(co*64 + cin0)*9 + r];
            s_w[r/9][co][r%9] = v;
        }
        __syncthreads();

        #pragma unroll 2
        for (int ci = 0; ci < 8; ci++) {
            float xr[3][6];
            #pragma unroll
            for (int dr = 0; dr < 3; dr++) {
                const float* rp = &s_in[ci][pr + dr][pc4];
                #pragma unroll
                for (int j = 0; j < 6; j++) xr[dr][j] = rp[j];
            }
            #pragma unroll
            for (int c = 0; c < NC; c++) {
                const float* wp = &s_w[ci][cg*NC + c][0];
                float wv[9];
                #pragma unroll
                for (int q = 0; q < 9; q++) wv[q] = wp[q];
                #pragma unroll
                for (int p = 0; p < 4; p++) {
                    float s = acc[c][p];
                    s += xr[0][p]*wv[0] + xr[0][p+1]*wv[1] + xr[0][p+2]*wv[2];
                    s += xr[1][p]*wv[3] + xr[1][p+1]*wv[4] + xr[1][p+2]*wv[5];
                    s += xr[2][p]*wv[6] + xr[2][p+1]*wv[7] + xr[2][p+2]*wv[8];
                    acc[c][p] = s;
                }
            }
        }
    }

    const int h = h0 + pr;
    #pragma unroll
    for (int c = 0; c < NC; c++) {
        const int co = cg*NC + c;
        if (co >= COUT) continue;
        float4 v = {acc[c][0], acc[c][1], acc[c][2], acc[c][3]};
        *(float4*)&out[((size_t)(b*COUT + co)*HH + h)*WW + w0 + pc4] = v;
    }
}

// ===========================================================================
// Adaptive filtering (unchanged, proven)
// ===========================================================================
__global__ __launch_bounds__(256) void filt_h_kernel(
    const float* __restrict__ filt, const float* __restrict__ base,
    float* __restrict__ fh)
{
    int idx = blockIdx.x * 256 + threadIdx.x;
    int w  = idx & 511;
    int h  = (idx >> 9) & 511;
    int bc = idx >> 18;
    int ch = bc % 3;
    int b  = bc / 3;

    const float* lp = filt + ((size_t)(b*30 + ch*10)*HH + h)*WW + w;
    float l[5];
    #pragma unroll
    for (int i = 0; i < 5; i++) l[i] = lp[(size_t)i*HWSZ];
    float m = fmaxf(fmaxf(fmaxf(l[0], l[1]), fmaxf(l[2], l[3])), l[4]);
    float e[5], s = 0.f;
    #pragma unroll
    for (int i = 0; i < 5; i++) { e[i] = __expf(l[i] - m); s += e[i]; }
    float inv = 1.f / s;

    const float* bp = base + (size_t)bc*HWSZ + w;
    float r = 0.f;
    #pragma unroll
    for (int i = 0; i < 5; i++) {
        int hh2 = h - 2 + i;
        float bv = (hh2 >= 0 && hh2 < HH) ? bp[(size_t)hh2*WW] : 0.f;
        r += bv * e[i] * inv;
    }
    fh[idx] = r;
}

__global__ __launch_bounds__(256) void filt_w_kernel(
    const float* __restrict__ filt, const float* __restrict__ fh,
    float* __restrict__ out)
{
    int idx = blockIdx.x * 256 + threadIdx.x;
    int w  = idx & 511;
    int h  = (idx >> 9) & 511;
    int bc = idx >> 18;
    int ch = bc % 3;
    int b  = bc / 3;

    const float* lp = filt + ((size_t)(b*30 + ch*10 + 5)*HH + h)*WW + w;
    float l[5];
    #pragma unroll
    for (int i = 0; i < 5; i++) l[i] = lp[(size_t)i*HWSZ];
    float m = fmaxf(fmaxf(fmaxf(l[0], l[1]), fmaxf(l[2], l[3])), l[4]);
    float e[5], s = 0.f;
    #pragma unroll
    for (int i = 0; i < 5; i++) { e[i] = __expf(l[i] - m); s += e[i]; }
    float inv = 1.f / s;

    const float* fp = fh + ((size_t)bc*HH + h)*WW;
    float r = 0.f;
    #pragma unroll
    for (int i = 0; i < 5; i++) {
        int ww2 = w - 2 + i;
        float fv = (ww2 >= 0 && ww2 < WW) ? fp[ww2] : 0.f;
        r += fv * e[i] * inv;
    }
    out[idx] = r;
}

// ===========================================================================
extern "C" void kernel_launch(void* const* d_in, const int* in_sizes, int n_in,
                              void* d_out, int out_size)
{
    const float* fm     = (const float*)d_in[0];
    const float* base   = (const float*)d_in[1];
    const float* wfirst = (const float*)d_in[2];
    const float* kbw1   = (const float*)d_in[3];
    const float* kbg1   = (const float*)d_in[4];
    const float* kbb1   = (const float*)d_in[5];
    const float* kbm1   = (const float*)d_in[6];
    const float* kbv1   = (const float*)d_in[7];
    const float* kbw2   = (const float*)d_in[8];
    const float* kbg2   = (const float*)d_in[9];
    const float* kbb2   = (const float*)d_in[10];
    const float* kbm2   = (const float*)d_in[11];
    const float* kbv2   = (const float*)d_in[12];
    const float* wlast  = (const float*)d_in[13];
    float* out = (float*)d_out;

    float *A, *F, *FHp;
    __nv_bfloat16 *P0h, *P0l, *P1h, *P1l, *P2h, *P2l, *Bg;
    cudaGetSymbolAddress((void**)&A,   g_bufA);
    cudaGetSymbolAddress((void**)&F,   g_filt);
    cudaGetSymbolAddress((void**)&FHp, g_fh);
    cudaGetSymbolAddress((void**)&P0h, g_P0h);
    cudaGetSymbolAddress((void**)&P0l, g_P0l);
    cudaGetSymbolAddress((void**)&P1h, g_P1h);
    cudaGetSymbolAddress((void**)&P1l, g_P1l);
    cudaGetSymbolAddress((void**)&P2h, g_P2h);
    cudaGetSymbolAddress((void**)&P2l, g_P2l);
    cudaGetSymbolAddress((void**)&Bg,  g_Bg);

    cudaFuncSetAttribute(res_conv_kernel<false,false>,
                         cudaFuncAttributeMaxDynamicSharedMemorySize, RES_SMEM);
    cudaFuncSetAttribute(res_conv_kernel<true,false>,
                         cudaFuncAttributeMaxDynamicSharedMemorySize, RES_SMEM);
    cudaFuncSetAttribute(res_conv_kernel<true,true>,
                         cudaFuncAttributeMaxDynamicSharedMemorySize, RES_SMEM);

    // 1. weight prep
    prep_w_kernel<<<(4*2*9*192*64 + 255)/256, 256>>>(kbw1, kbw2, Bg);

    // 2. conv_first -> P0 pair
    dim3 g7(WW/16, HH/8, BATCH);
    conv7x7_kernel<<<g7, 256>>>(fm, wfirst, P0h, P0l);

    // 3. residual blocks (tensor cores via mma.sync)
    dim3 gr(WW/128, HH, BATCH);
    const size_t SL = (size_t)9*192*64;  // per (r, conv) weight stride
    __nv_bfloat16 *yh = P0h, *yl = P0l;
    __nv_bfloat16 *alt_h = P2h, *alt_l = P2l;
    for (int r = 0; r < 4; r++) {
        res_conv_kernel<false,false><<<gr, 256, RES_SMEM>>>(
            yh, yl, Bg + (size_t)(r*2+0)*SL,
            kbg1 + r*64, kbb1 + r*64, kbm1 + r*64, kbv1 + r*64,
            nullptr, nullptr, P1h, P1l, nullptr);
        if (r == 3) {
            res_conv_kernel<true,true><<<gr, 256, RES_SMEM>>>(
                P1h, P1l, Bg + (size_t)(r*2+1)*SL,
                kbg2 + r*64, kbb2 + r*64, kbm2 + r*64, kbv2 + r*64,
                yh, yl, nullptr, nullptr, A);
        } else {
            res_conv_kernel<true,false><<<gr, 256, RES_SMEM>>>(
                P1h, P1l, Bg + (size_t)(r*2+1)*SL,
                kbg2 + r*64, kbb2 + r*64, kbm2 + r*64, kbv2 + r*64,
                yh, yl, alt_h, alt_l, nullptr);
            __nv_bfloat16* th = yh; __nv_bfloat16* tl = yl;
            yh = alt_h; yl = alt_l;
            alt_h = th; alt_l = tl;
        }
    }

    // 4. conv_last
    conv_last_kernel<<<g7, 256>>>(A, wlast, F);

    // 5. adaptive filtering
    int npix = BATCH*3*HWSZ;
    filt_h_kernel<<<npix/256, 256>>>(F, base, FHp);
    filt_w_kernel<<<npix/256, 256>>>(F, FHp, out);
}

// round 8
// speedup vs baseline: 2.5427x; 1.1158x over previous
#include <cuda_runtime.h>
#include <cuda_bf16.h>
#include <cstdint>

#define HH 512
#define WW 512
#define BATCH 2
#define HWSZ (HH*WW)

// ===========================================================================
// Warp-MMA helpers (family-compatible: ldmatrix sm_75+, bf16 mma.sync sm_80+)
// ===========================================================================
__device__ __forceinline__ uint32_t smem_u32(const void* p) {
    uint32_t a;
    asm("{ .reg .u64 t; cvta.to.shared.u64 t, %1; cvt.u32.u64 %0, t; }"
        : "=r"(a) : "l"(p));
    return a;
}
__device__ __forceinline__ void ldsm_x4(uint32_t* r, uint32_t addr) {
    asm volatile("ldmatrix.sync.aligned.m8n8.x4.shared.b16 {%0,%1,%2,%3}, [%4];"
        : "=r"(r[0]), "=r"(r[1]), "=r"(r[2]), "=r"(r[3]) : "r"(addr));
}
__device__ __forceinline__ void ldsm_x4_t(uint32_t* r, uint32_t addr) {
    asm volatile("ldmatrix.sync.aligned.m8n8.x4.trans.shared.b16 {%0,%1,%2,%3}, [%4];"
        : "=r"(r[0]), "=r"(r[1]), "=r"(r[2]), "=r"(r[3]) : "r"(addr));
}
__device__ __forceinline__ void mma_bf16(float* d, const uint32_t* a,
                                         uint32_t b0, uint32_t b1) {
    asm volatile("mma.sync.aligned.m16n8k16.row.col.f32.bf16.bf16.f32 "
        "{%0,%1,%2,%3}, {%4,%5,%6,%7}, {%8,%9}, {%0,%1,%2,%3};"
        : "+f"(d[0]), "+f"(d[1]), "+f"(d[2]), "+f"(d[3])
        : "r"(a[0]), "r"(a[1]), "r"(a[2]), "r"(a[3]), "r"(b0), "r"(b1));
}
// XOR swizzle for 128B-row tiles (B smem)
__device__ __forceinline__ uint32_t swzB(uint32_t off) {
    return off ^ ((off >> 3) & 0x70);
}
// swizzle for 256B-row tiles (A smem): chunk' = (c&8) | ((c^row)&7)
__device__ __forceinline__ uint32_t swzA(int row, int kbyte) {
    int c = kbyte >> 4;
    int cs = (c & 8) | ((c ^ row) & 7);
    return (uint32_t)(row * 256 + (cs << 4));
}

// ===========================================================================
// Persistent scratch
// ===========================================================================
__device__ float g_bufA[(size_t)BATCH*64*HWSZ];     // fp32 NCHW (final block out)
__device__ float g_filt[(size_t)BATCH*30*HWSZ];
__device__ float g_fh[(size_t)BATCH*3*HWSZ];
// NHWC bf16 activation pairs [b][h][w][c]
__device__ __nv_bfloat16 g_P0h[(size_t)BATCH*HWSZ*64];
__device__ __nv_bfloat16 g_P0l[(size_t)BATCH*HWSZ*64];
__device__ __nv_bfloat16 g_P1h[(size_t)BATCH*HWSZ*64];
__device__ __nv_bfloat16 g_P1l[(size_t)BATCH*HWSZ*64];
__device__ __nv_bfloat16 g_P2h[(size_t)BATCH*HWSZ*64];
__device__ __nv_bfloat16 g_P2l[(size_t)BATCH*HWSZ*64];
// prepped weights [rc=4*2][tap=9][k=128][cout=64] bf16; k: [wh(64)|wl(64)] over cin
__device__ __nv_bfloat16 g_Bg[(size_t)4*2*9*128*64];

// ===========================================================================
// Weight prep
// ===========================================================================
__global__ void prep_w_kernel(const float* __restrict__ w1, const float* __restrict__ w2,
                              __nv_bfloat16* __restrict__ Bg)
{
    int idx = blockIdx.x * 256 + threadIdx.x;
    if (idx >= 4*2*9*128*64) return;
    int co  = idx & 63;
    int k   = (idx >> 6) % 128;
    int tap = (idx >> 6) / 128 % 9;
    int rc  = idx / (128*64*9);
    int conv = rc & 1, r = rc >> 1;
    int cin = (k < 64) ? k : (k - 64);
    int ky = tap / 3, kx = tap % 3;
    const float* src = conv ? w2 : w1;
    float v = src[(((r*64 + co)*64 + cin)*3 + ky)*3 + kx];
    __nv_bfloat16 h = __float2bfloat16(v);
    if (k < 64) Bg[idx] = h;
    else        Bg[idx] = __float2bfloat16(v - __bfloat162float(h));
}

// ===========================================================================
// conv 7x7, Cin=6 -> 64, pad 3, ReLU. Scalar fp32; outputs NHWC bf16 hi/lo.
// ===========================================================================
__global__ __launch_bounds__(256) void conv7x7_kernel(
    const float* __restrict__ in, const float* __restrict__ wt,
    __nv_bfloat16* __restrict__ out_hi, __nv_bfloat16* __restrict__ out_lo)
{
    __shared__ float s_in[6][14][24];
    __shared__ float s_w[64][7][8];

    const int tid  = threadIdx.x;
    const int cg   = tid >> 5;
    const int slot = tid & 31;
    const int pr   = slot >> 2;
    const int pc4  = (slot & 3) * 4;
    const int h0   = blockIdx.y * 8;
    const int w0   = blockIdx.x * 16;
    const int b    = blockIdx.z;

    for (int i = tid; i < 6*14*22; i += 256) {
        int ci = i / (14*22);
        int r  = (i / 22) % 14;
        int c  = i % 22;
        int gh = h0 - 3 + r;
        int gw = w0 - 3 + c;
        float v = 0.f;
        if (gh >= 0 && gh < HH && gw >= 0 && gw < WW)
            v = in[((b*6 + ci)*HH + gh)*WW + gw];
        s_in[ci][r][c] = v;
    }

    float acc[8][4];
    #pragma unroll
    for (int c = 0; c < 8; c++)
        #pragma unroll
        for (int p = 0; p < 4; p++) acc[c][p] = 0.f;

    for (int cin = 0; cin < 6; cin++) {
        __syncthreads();
        for (int i = tid; i < 64*49; i += 256) {
            int co = i / 49, k = i % 49;
            s_w[co][k/7][k%7] = wt[(co*6 + cin)*49 + k];
        }
        __syncthreads();
        #pragma unroll 1
        for (int ky = 0; ky < 7; ky++) {
            float xr[10];
            const float* rp = &s_in[cin][pr + ky][pc4];
            #pragma unroll
            for (int j = 0; j < 10; j++) xr[j] = rp[j];
            #pragma unroll
            for (int c = 0; c < 8; c++) {
                const float* wp = &s_w[cg*8 + c][ky][0];
                float wv[7];
                #pragma unroll
                for (int q = 0; q < 7; q++) wv[q] = wp[q];
                #pragma unroll
                for (int p = 0; p < 4; p++) {
                    float s = acc[c][p];
                    #pragma unroll
                    for (int q = 0; q < 7; q++) s += xr[p+q] * wv[q];
                    acc[c][p] = s;
                }
            }
        }
    }

    const int h = h0 + pr;
    #pragma unroll
    for (int p = 0; p < 4; p++) {
        int w = w0 + pc4 + p;
        size_t nb = ((size_t)((b*HH + h)*WW + w))*64 + cg*8;
        union { uint4 u; __nv_bfloat16 x[8]; } Uh, Ul;
        #pragma unroll
        for (int c = 0; c < 8; c++) {
            float v = fmaxf(acc[c][p], 0.f);
            __nv_bfloat16 hh = __float2bfloat16(v);
            Uh.x[c] = hh;
            Ul.x[c] = __float2bfloat16(v - __bfloat162float(hh));
        }
        *(uint4*)(out_hi + nb) = Uh.u;
        *(uint4*)(out_lo + nb) = Ul.u;
    }
}

// ===========================================================================
// Residual conv3x3 64->64 via mma.sync bf16 (3-term split, fp32 accum).
// CTA: 128 thr = 4 warps, each M=32 pixels x N=64 couts (tile M=128, N=64).
// A smem: 130px window x ([yh 128B | yl 128B]); B smem per tap: [wh 64 | wl 64].
// Pass order per tap: yh*wh -> yh*wl (A frags held) -> yl*wh.
// ===========================================================================
#define RES_SMEM (130*256 + 128*128 + 512)

template<bool SKIP, bool OUTF32>
__global__ __launch_bounds__(128) void res_conv_kernel(
    const __nv_bfloat16* __restrict__ in_hi, const __nv_bfloat16* __restrict__ in_lo,
    const __nv_bfloat16* __restrict__ Bg,
    const float* __restrict__ bng, const float* __restrict__ bnb,
    const float* __restrict__ bnm, const float* __restrict__ bnv,
    const __nv_bfloat16* __restrict__ sk_hi, const __nv_bfloat16* __restrict__ sk_lo,
    __nv_bfloat16* __restrict__ out_hi, __nv_bfloat16* __restrict__ out_lo,
    float* __restrict__ out_f32)
{
    extern __shared__ __align__(16) unsigned char dynsmem[];
    unsigned char* sA = dynsmem;                 // 130 rows x 256B
    unsigned char* sB = dynsmem + 130*256;       // 128 rows x 128B
    float* s_sc = (float*)(dynsmem + 130*256 + 128*128);
    float* s_sh = s_sc + 64;

    const int tid  = threadIdx.x;
    const int wm   = tid >> 5;      // M-warp: pixels wm*32..+31
    const int lane = tid & 31;
    const int w0   = blockIdx.x * 128;
    const int h    = blockIdx.y;
    const int b    = blockIdx.z;

    const uint32_t aA = smem_u32(sA);
    const uint32_t aB = smem_u32(sB);

    if (tid < 64) {
        float sc = bng[tid] * rsqrtf(bnv[tid] + 1e-5f);
        s_sc[tid] = sc;
        s_sh[tid] = bnb[tid] - bnm[tid] * sc;
    }

    float d[2][8][4];
    #pragma unroll
    for (int mf = 0; mf < 2; mf++)
        #pragma unroll
        for (int nf = 0; nf < 8; nf++)
            #pragma unroll
            for (int q = 0; q < 4; q++) d[mf][nf][q] = 0.f;

    for (int ky = 0; ky < 3; ky++) {
        const int hs = h + ky - 1;
        const bool hok = (hs >= 0) && (hs < HH);
        __syncthreads();   // all prior-tap smem reads complete
        // ---- stage A window: 130 rows x (hi 128B | lo 128B) ----
        for (int idx = tid; idx < 260; idx += 128) {
            int r = idx % 130;
            int half = idx / 130;
            int ws = w0 - 1 + r;
            bool ok = hok && (ws >= 0) && (ws < WW);
            const uint4* src = (const uint4*)((half ? in_lo : in_hi)
                               + ((size_t)((b*HH + hs)*WW + ws))*64);
            #pragma unroll
            for (int j = 0; j < 8; j++) {
                uint4 v = ok ? src[j] : make_uint4(0u,0u,0u,0u);
                *(uint4*)(sA + swzA(r, half*128 + j*16)) = v;
            }
        }
        for (int kx = 0; kx < 3; kx++) {
            const int tap = ky*3 + kx;
            if (kx) __syncthreads();   // prior kx reads done before B overwrite
            // ---- stage B tap: 128 rows x 128B ([wh|wl]) ----
            {
                const __nv_bfloat16* bt = Bg + (size_t)tap*128*64;
                for (int idx = tid; idx < 1024; idx += 128) {
                    int kr = idx >> 3, c = idx & 7;
                    uint4 v = *(const uint4*)(bt + (size_t)kr*64 + c*8);
                    *(uint4*)(sB + swzB(kr*128 + c*16)) = v;
                }
            }
            __syncthreads();

            // ---- held A_yh fragments (4 k-slices x 2 m-frags) ----
            uint32_t Ah[4][2][4];
            #pragma unroll
            for (int j = 0; j < 4; j++)
                #pragma unroll
                for (int mf = 0; mf < 2; mf++) {
                    int arow = wm*32 + mf*16 + (lane & 15) + kx;
                    ldsm_x4(Ah[j][mf], aA + swzA(arow, j*32 + (lane >> 4)*16));
                }
            // ---- pass 1: yh x wh (B rows 0-63) ----
            #pragma unroll
            for (int j = 0; j < 4; j++) {
                uint32_t bf[4][4];
                const int krow = j*16 + (lane & 15);
                #pragma unroll
                for (int bq = 0; bq < 4; bq++)
                    ldsm_x4_t(bf[bq], aB + swzB(krow*128 + bq*32 + (lane >> 4)*16));
                #pragma unroll
                for (int mf = 0; mf < 2; mf++)
                    #pragma unroll
                    for (int nf = 0; nf < 8; nf++)
                        mma_bf16(d[mf][nf], Ah[j][mf],
                                 bf[nf >> 1][(nf & 1)*2], bf[nf >> 1][(nf & 1)*2 + 1]);
            }
            // ---- pass 2: yh x wl (B rows 64-127), A frags reused ----
            #pragma unroll
            for (int j = 0; j < 4; j++) {
                uint32_t bf[4][4];
                const int krow = 64 + j*16 + (lane & 15);
                #pragma unroll
                for (int bq = 0; bq < 4; bq++)
                    ldsm_x4_t(bf[bq], aB + swzB(krow*128 + bq*32 + (lane >> 4)*16));
                #pragma unroll
                for (int mf = 0; mf < 2; mf++)
                    #pragma unroll
                    for (int nf = 0; nf < 8; nf++)
                        mma_bf16(d[mf][nf], Ah[j][mf],
                                 bf[nf >> 1][(nf & 1)*2], bf[nf >> 1][(nf & 1)*2 + 1]);
            }
            // ---- pass 3: yl x wh ----
            #pragma unroll
            for (int j = 0; j < 4; j++) {
                uint32_t Al[2][4];
                #pragma unroll
                for (int mf = 0; mf < 2; mf++) {
                    int arow = wm*32 + mf*16 + (lane & 15) + kx;
                    ldsm_x4(Al[mf], aA + swzA(arow, 128 + j*32 + (lane >> 4)*16));
                }
                uint32_t bf[4][4];
                const int krow = j*16 + (lane & 15);
                #pragma unroll
                for (int bq = 0; bq < 4; bq++)
                    ldsm_x4_t(bf[bq], aB + swzB(krow*128 + bq*32 + (lane >> 4)*16));
                #pragma unroll
                for (int mf = 0; mf < 2; mf++)
                    #pragma unroll
                    for (int nf = 0; nf < 8; nf++)
                        mma_bf16(d[mf][nf], Al[mf],
                                 bf[nf >> 1][(nf & 1)*2], bf[nf >> 1][(nf & 1)*2 + 1]);
            }
        }
    }

    // ---- epilogue: BN + ReLU (+skip), emit bf16 pair NHWC or fp32 NCHW ----
    #pragma unroll
    for (int mf = 0; mf < 2; mf++) {
        #pragma unroll
        for (int rr = 0; rr < 2; rr++) {
            const int p = wm*32 + mf*16 + (lane >> 2) + rr*8;
            const int w = w0 + p;
            const size_t nbase = ((size_t)((b*HH + h)*WW + w))*64;
            #pragma unroll
            for (int nf = 0; nf < 8; nf++) {
                const int cout = nf*8 + (lane & 3)*2;
                float v0 = d[mf][nf][rr*2 + 0] * s_sc[cout]     + s_sh[cout];
                float v1 = d[mf][nf][rr*2 + 1] * s_sc[cout + 1] + s_sh[cout + 1];
                v0 = fmaxf(v0, 0.f);
                v1 = fmaxf(v1, 0.f);
                if (SKIP) {
                    uint32_t sh2 = *(const uint32_t*)(sk_hi + nbase + cout);
                    uint32_t sl2 = *(const uint32_t*)(sk_lo + nbase + cout);
                    v0 += __bfloat162float(__ushort_as_bfloat16((unsigned short)(sh2 & 0xFFFF)))
                        + __bfloat162float(__ushort_as_bfloat16((unsigned short)(sl2 & 0xFFFF)));
                    v1 += __bfloat162float(__ushort_as_bfloat16((unsigned short)(sh2 >> 16)))
                        + __bfloat162float(__ushort_as_bfloat16((unsigned short)(sl2 >> 16)));
                }
                if (OUTF32) {
                    out_f32[((size_t)(b*64 + cout    )*HH + h)*WW + w] = v0;
                    out_f32[((size_t)(b*64 + cout + 1)*HH + h)*WW + w] = v1;
                } else {
                    __nv_bfloat16 h0 = __float2bfloat16(v0);
                    __nv_bfloat16 h1 = __float2bfloat16(v1);
                    __nv_bfloat16 l0 = __float2bfloat16(v0 - __bfloat162float(h0));
                    __nv_bfloat16 l1 = __float2bfloat16(v1 - __bfloat162float(h1));
                    uint32_t ph = (uint32_t)__bfloat16_as_ushort(h0)
                                | ((uint32_t)__bfloat16_as_ushort(h1) << 16);
                    uint32_t pl = (uint32_t)__bfloat16_as_ushort(l0)
                                | ((uint32_t)__bfloat16_as_ushort(l1) << 16);
                    *(uint32_t*)(out_hi + nbase + cout) = ph;
                    *(uint32_t*)(out_lo + nbase + cout) = pl;
                }
            }
        }
    }
}

// ===========================================================================
// conv_last: scalar 3x3, 64 -> 30 (fp32 NCHW in/out)
// ===========================================================================
__global__ __launch_bounds__(256) void conv_last_kernel(
    const float* __restrict__ in, const float* __restrict__ wt,
    float* __restrict__ out)
{
    constexpr int NC = 4, COUT = 30, CP = 32;
    __shared__ float s_in[8][10][20];
    __shared__ float s_w[8][CP][12];

    const int tid  = threadIdx.x;
    const int cg   = tid >> 5;
    const int slot = tid & 31;
    const int pr   = slot >> 2;
    const int pc4  = (slot & 3) * 4;
    const int h0   = blockIdx.y * 8;
    const int w0   = blockIdx.x * 16;
    const int b    = blockIdx.z;

    float acc[NC][4];
    #pragma unroll
    for (int c = 0; c < NC; c++)
        #pragma unroll
        for (int p = 0; p < 4; p++) acc[c][p] = 0.f;

    for (int cc = 0; cc < 8; cc++) {
        const int cin0 = cc * 8;
        __syncthreads();
        for (int i = tid; i < 8*10*18; i += 256) {
            int ci = i / 180;
            int r  = (i / 18) % 10;
            int c  = i % 18;
            int gh = h0 - 1 + r;
            int gw = w0 - 1 + c;
            float v = 0.f;
            if (gh >= 0 && gh < HH && gw >= 0 && gw < WW)
                v = in[((size_t)(b*64 + cin0 + ci)*HH + gh)*WW + gw];
            s_in[ci][r][c] = v;
        }
        for (int i = tid; i < CP*72; i += 256) {
            int co = i / 72;
            int r  = i % 72;
            float v = 0.f;
            if (co < COUT) v = wt[(co*64 + cin0)*9 + r];
            s_w[r/9][co][r%9] = v;
        }
        __syncthreads();

        #pragma unroll 2
        for (int ci = 0; ci < 8; ci++) {
            float xr[3][6];
            #pragma unroll
            for (int dr = 0; dr < 3; dr++) {
                const float* rp = &s_in[ci][pr + dr][pc4];
                #pragma unroll
                for (int j = 0; j < 6; j++) xr[dr][j] = rp[j];
            }
            #pragma unroll
            for (int c = 0; c < NC; c++) {
                const float* wp = &s_w[ci][cg*NC + c][0];
                float wv[9];
                #pragma unroll
                for (int q = 0; q < 9; q++) wv[q] = wp[q];
                #pragma unroll
                for (int p = 0; p < 4; p++) {
                    float s = acc[c][p];
                    s += xr[0][p]*wv[0] + xr[0][p+1]*wv[1] + xr[0][p+2]*wv[2];
                    s += xr[1][p]*wv[3] + xr[1][p+1]*wv[4] + xr[1][p+2]*wv[5];
                    s += xr[2][p]*wv[6] + xr[2][p+1]*wv[7] + xr[2][p+2]*wv[8];
                    acc[c][p] = s;
                }
            }
        }
    }

    const int h = h0 + pr;
    #pragma unroll
    for (int c = 0; c < NC; c++) {
        const int co = cg*NC + c;
        if (co >= COUT) continue;
        float4 v = {acc[c][0], acc[c][1], acc[c][2], acc[c][3]};
        *(float4*)&out[((size_t)(b*COUT + co)*HH + h)*WW + w0 + pc4] = v;
    }
}

// ===========================================================================
// Adaptive filtering
// ===========================================================================
__global__ __launch_bounds__(256) void filt_h_kernel(
    const float* __restrict__ filt, const float* __restrict__ base,
    float* __restrict__ fh)
{
    int idx = blockIdx.x * 256 + threadIdx.x;
    int w  = idx & 511;
    int h  = (idx >> 9) & 511;
    int bc = idx >> 18;
    int ch = bc % 3;
    int b  = bc / 3;

    const float* lp = filt + ((size_t)(b*30 + ch*10)*HH + h)*WW + w;
    float l[5];
    #pragma unroll
    for (int i = 0; i < 5; i++) l[i] = lp[(size_t)i*HWSZ];
    float m = fmaxf(fmaxf(fmaxf(l[0], l[1]), fmaxf(l[2], l[3])), l[4]);
    float e[5], s = 0.f;
    #pragma unroll
    for (int i = 0; i < 5; i++) { e[i] = __expf(l[i] - m); s += e[i]; }
    float inv = 1.f / s;

    const float* bp = base + (size_t)bc*HWSZ + w;
    float r = 0.f;
    #pragma unroll
    for (int i = 0; i < 5; i++) {
        int hh2 = h - 2 + i;
        float bv = (hh2 >= 0 && hh2 < HH) ? bp[(size_t)hh2*WW] : 0.f;
        r += bv * e[i] * inv;
    }
    fh[idx] = r;
}

__global__ __launch_bounds__(256) void filt_w_kernel(
    const float* __restrict__ filt, const float* __restrict__ fh,
    float* __restrict__ out)
{
    int idx = blockIdx.x * 256 + threadIdx.x;
    int w  = idx & 511;
    int h  = (idx >> 9) & 511;
    int bc = idx >> 18;
    int ch = bc % 3;
    int b  = bc / 3;

    const float* lp = filt + ((size_t)(b*30 + ch*10 + 5)*HH + h)*WW + w;
    float l[5];
    #pragma unroll
    for (int i = 0; i < 5; i++) l[i] = lp[(size_t)i*HWSZ];
    float m = fmaxf(fmaxf(fmaxf(l[0], l[1]), fmaxf(l[2], l[3])), l[4]);
    float e[5], s = 0.f;
    #pragma unroll
    for (int i = 0; i < 5; i++) { e[i] = __expf(l[i] - m); s += e[i]; }
    float inv = 1.f / s;

    const float* fp = fh + ((size_t)bc*HH + h)*WW;
    float r = 0.f;
    #pragma unroll
    for (int i = 0; i < 5; i++) {
        int ww2 = w - 2 + i;
        float fv = (ww2 >= 0 && ww2 < WW) ? fp[ww2] : 0.f;
        r += fv * e[i] * inv;
    }
    out[idx] = r;
}

// ===========================================================================
extern "C" void kernel_launch(void* const* d_in, const int* in_sizes, int n_in,
                              void* d_out, int out_size)
{
    const float* fm     = (const float*)d_in[0];
    const float* base   = (const float*)d_in[1];
    const float* wfirst = (const float*)d_in[2];
    const float* kbw1   = (const float*)d_in[3];
    const float* kbg1   = (const float*)d_in[4];
    const float* kbb1   = (const float*)d_in[5];
    const float* kbm1   = (const float*)d_in[6];
    const float* kbv1   = (const float*)d_in[7];
    const float* kbw2   = (const float*)d_in[8];
    const float* kbg2   = (const float*)d_in[9];
    const float* kbb2   = (const float*)d_in[10];
    const float* kbm2   = (const float*)d_in[11];
    const float* kbv2   = (const float*)d_in[12];
    const float* wlast  = (const float*)d_in[13];
    float* out = (float*)d_out;

    float *A, *F, *FHp;
    __nv_bfloat16 *P0h, *P0l, *P1h, *P1l, *P2h, *P2l, *Bg;
    cudaGetSymbolAddress((void**)&A,   g_bufA);
    cudaGetSymbolAddress((void**)&F,   g_filt);
    cudaGetSymbolAddress((void**)&FHp, g_fh);
    cudaGetSymbolAddress((void**)&P0h, g_P0h);
    cudaGetSymbolAddress((void**)&P0l, g_P0l);
    cudaGetSymbolAddress((void**)&P1h, g_P1h);
    cudaGetSymbolAddress((void**)&P1l, g_P1l);
    cudaGetSymbolAddress((void**)&P2h, g_P2h);
    cudaGetSymbolAddress((void**)&P2l, g_P2l);
    cudaGetSymbolAddress((void**)&Bg,  g_Bg);

    cudaFuncSetAttribute(res_conv_kernel<false,false>,
                         cudaFuncAttributeMaxDynamicSharedMemorySize, RES_SMEM);
    cudaFuncSetAttribute(res_conv_kernel<true,false>,
                         cudaFuncAttributeMaxDynamicSharedMemorySize, RES_SMEM);
    cudaFuncSetAttribute(res_conv_kernel<true,true>,
                         cudaFuncAttributeMaxDynamicSharedMemorySize, RES_SMEM);

    // 1. weight prep
    prep_w_kernel<<<(4*2*9*128*64 + 255)/256, 256>>>(kbw1, kbw2, Bg);

    // 2. conv_first -> P0 pair
    dim3 g7(WW/16, HH/8, BATCH);
    conv7x7_kernel<<<g7, 256>>>(fm, wfirst, P0h, P0l);

    // 3. residual blocks (tensor cores via mma.sync)
    dim3 gr(WW/128, HH, BATCH);
    const size_t SL = (size_t)9*128*64;  // per (r, conv) weight stride
    __nv_bfloat16 *yh = P0h, *yl = P0l;
    __nv_bfloat16 *alt_h = P2h, *alt_l = P2l;
    for (int r = 0; r < 4; r++) {
        res_conv_kernel<false,false><<<gr, 128, RES_SMEM>>>(
            yh, yl, Bg + (size_t)(r*2+0)*SL,
            kbg1 + r*64, kbb1 + r*64, kbm1 + r*64, kbv1 + r*64,
            nullptr, nullptr, P1h, P1l, nullptr);
        if (r == 3) {
            res_conv_kernel<true,true><<<gr, 128, RES_SMEM>>>(
                P1h, P1l, Bg + (size_t)(r*2+1)*SL,
                kbg2 + r*64, kbb2 + r*64, kbm2 + r*64, kbv2 + r*64,
                yh, yl, nullptr, nullptr, A);
        } else {
            res_conv_kernel<true,false><<<gr, 128, RES_SMEM>>>(
                P1h, P1l, Bg + (size_t)(r*2+1)*SL,
                kbg2 + r*64, kbb2 + r*64, kbm2 + r*64, kbv2 + r*64,
                yh, yl, alt_h, alt_l, nullptr);
            __nv_bfloat16* th = yh; __nv_bfloat16* tl = yl;
            yh = alt_h; yl = alt_l;
            alt_h = th; alt_l = tl;
        }
    }

    // 4. conv_last
    conv_last_kernel<<<g7, 256>>>(A, wlast, F);

    // 5. adaptive filtering
    int npix = BATCH*3*HWSZ;
    filt_h_kernel<<<npix/256, 256>>>(F, base, FHp);
    filt_w_kernel<<<npix/256, 256>>>(F, FHp, out);
}

// round 10
// speedup vs baseline: 3.1562x; 1.2413x over previous
#include <cuda_runtime.h>
#include <cuda_bf16.h>
#include <cstdint>

#define HH 512
#define WW 512
#define BATCH 2
#define HWSZ (HH*WW)

// ===========================================================================
// Warp-MMA + cp.async helpers (family-compatible)
// ===========================================================================
__device__ __forceinline__ uint32_t smem_u32(const void* p) {
    uint32_t a;
    asm("{ .reg .u64 t; cvta.to.shared.u64 t, %1; cvt.u32.u64 %0, t; }"
        : "=r"(a) : "l"(p));
    return a;
}
__device__ __forceinline__ void ldsm_x4(uint32_t* r, uint32_t addr) {
    asm volatile("ldmatrix.sync.aligned.m8n8.x4.shared.b16 {%0,%1,%2,%3}, [%4];"
        : "=r"(r[0]), "=r"(r[1]), "=r"(r[2]), "=r"(r[3]) : "r"(addr));
}
__device__ __forceinline__ void ldsm_x4_t(uint32_t* r, uint32_t addr) {
    asm volatile("ldmatrix.sync.aligned.m8n8.x4.trans.shared.b16 {%0,%1,%2,%3}, [%4];"
        : "=r"(r[0]), "=r"(r[1]), "=r"(r[2]), "=r"(r[3]) : "r"(addr));
}
__device__ __forceinline__ void mma_bf16(float* d, const uint32_t* a,
                                         uint32_t b0, uint32_t b1) {
    asm volatile("mma.sync.aligned.m16n8k16.row.col.f32.bf16.bf16.f32 "
        "{%0,%1,%2,%3}, {%4,%5,%6,%7}, {%8,%9}, {%0,%1,%2,%3};"
        : "+f"(d[0]), "+f"(d[1]), "+f"(d[2]), "+f"(d[3])
        : "r"(a[0]), "r"(a[1]), "r"(a[2]), "r"(a[3]), "r"(b0), "r"(b1));
}
__device__ __forceinline__ void cpa16(uint32_t dst, const void* src) {
    asm volatile("cp.async.cg.shared.global [%0], [%1], 16;"
                 :: "r"(dst), "l"(src) : "memory");
}
__device__ __forceinline__ void cpa16z(uint32_t dst, const void* src, int ok) {
    asm volatile("cp.async.cg.shared.global [%0], [%1], 16, %2;"
                 :: "r"(dst), "l"(src), "r"(ok ? 16 : 0) : "memory");
}
#define CP_COMMIT() asm volatile("cp.async.commit_group;" ::: "memory")
#define CP_WAIT0()  asm volatile("cp.async.wait_group 0;" ::: "memory")

// XOR swizzle for 128B-row tiles (B smem)
__device__ __forceinline__ uint32_t swzB(uint32_t off) {
    return off ^ ((off >> 3) & 0x70);
}
// swizzle for 256B-row tiles (A smem): chunk' = (c&8) | ((c^row)&7)
__device__ __forceinline__ uint32_t swzA(int row, int kbyte) {
    int c = kbyte >> 4;
    int cs = (c & 8) | ((c ^ row) & 7);
    return (uint32_t)(row * 256 + (cs << 4));
}

// ===========================================================================
// Persistent scratch
// ===========================================================================
__device__ float g_filt[(size_t)BATCH*30*HWSZ];
__device__ float g_fh[(size_t)BATCH*3*HWSZ];
// NHWC bf16 activation pairs [b][h][w][c]
__device__ __nv_bfloat16 g_P0h[(size_t)BATCH*HWSZ*64];
__device__ __nv_bfloat16 g_P0l[(size_t)BATCH*HWSZ*64];
__device__ __nv_bfloat16 g_P1h[(size_t)BATCH*HWSZ*64];
__device__ __nv_bfloat16 g_P1l[(size_t)BATCH*HWSZ*64];
__device__ __nv_bfloat16 g_P2h[(size_t)BATCH*HWSZ*64];
__device__ __nv_bfloat16 g_P2l[(size_t)BATCH*HWSZ*64];
// prepped weights: 9 sections (8 res convs + conv_last padded) x [tap][k=128][cout=64]
// k: [wh(64) | wl(64)] over cin
__device__ __nv_bfloat16 g_Bg[(size_t)9*9*128*64];

// ===========================================================================
// Weight prep
// ===========================================================================
__global__ void prep_w_kernel(const float* __restrict__ w1, const float* __restrict__ w2,
                              const float* __restrict__ wlast,
                              __nv_bfloat16* __restrict__ Bg)
{
    int idx = blockIdx.x * 256 + threadIdx.x;
    if (idx >= 9*9*128*64) return;
    int co  = idx & 63;
    int k   = (idx >> 6) % 128;
    int tap = (idx >> 6) / 128 % 9;
    int rc  = idx / (128*64*9);
    int cin = (k < 64) ? k : (k - 64);
    int ky = tap / 3, kx = tap % 3;
    float v;
    if (rc < 8) {
        int conv = rc & 1, r = rc >> 1;
        const float* src = conv ? w2 : w1;
        v = src[(((r*64 + co)*64 + cin)*3 + ky)*3 + kx];
    } else {
        v = (co < 30) ? wlast[((co*64 + cin)*3 + ky)*3 + kx] : 0.f;
    }
    __nv_bfloat16 h = __float2bfloat16(v);
    if (k < 64) Bg[idx] = h;
    else        Bg[idx] = __float2bfloat16(v - __bfloat162float(h));
}

// ===========================================================================
// conv 7x7, Cin=6 -> 64, pad 3, ReLU. Scalar fp32; outputs NHWC bf16 hi/lo.
// ===========================================================================
__global__ __launch_bounds__(256) void conv7x7_kernel(
    const float* __restrict__ in, const float* __restrict__ wt,
    __nv_bfloat16* __restrict__ out_hi, __nv_bfloat16* __restrict__ out_lo)
{
    __shared__ float s_in[6][14][24];
    __shared__ float s_w[64][7][8];

    const int tid  = threadIdx.x;
    const int cg   = tid >> 5;
    const int slot = tid & 31;
    const int pr   = slot >> 2;
    const int pc4  = (slot & 3) * 4;
    const int h0   = blockIdx.y * 8;
    const int w0   = blockIdx.x * 16;
    const int b    = blockIdx.z;

    for (int i = tid; i < 6*14*22; i += 256) {
        int ci = i / (14*22);
        int r  = (i / 22) % 14;
        int c  = i % 22;
        int gh = h0 - 3 + r;
        int gw = w0 - 3 + c;
        float v = 0.f;
        if (gh >= 0 && gh < HH && gw >= 0 && gw < WW)
            v = in[((b*6 + ci)*HH + gh)*WW + gw];
        s_in[ci][r][c] = v;
    }

    float acc[8][4];
    #pragma unroll
    for (int c = 0; c < 8; c++)
        #pragma unroll
        for (int p = 0; p < 4; p++) acc[c][p] = 0.f;

    for (int cin = 0; cin < 6; cin++) {
        __syncthreads();
        for (int i = tid; i < 64*49; i += 256) {
            int co = i / 49, k = i % 49;
            s_w[co][k/7][k%7] = wt[(co*6 + cin)*49 + k];
        }
        __syncthreads();
        #pragma unroll 1
        for (int ky = 0; ky < 7; ky++) {
            float xr[10];
            const float* rp = &s_in[cin][pr + ky][pc4];
            #pragma unroll
            for (int j = 0; j < 10; j++) xr[j] = rp[j];
            #pragma unroll
            for (int c = 0; c < 8; c++) {
                const float* wp = &s_w[cg*8 + c][ky][0];
                float wv[7];
                #pragma unroll
                for (int q = 0; q < 7; q++) wv[q] = wp[q];
                #pragma unroll
                for (int p = 0; p < 4; p++) {
                    float s = acc[c][p];
                    #pragma unroll
                    for (int q = 0; q < 7; q++) s += xr[p+q] * wv[q];
                    acc[c][p] = s;
                }
            }
        }
    }

    const int h = h0 + pr;
    #pragma unroll
    for (int p = 0; p < 4; p++) {
        int w = w0 + pc4 + p;
        size_t nb = ((size_t)((b*HH + h)*WW + w))*64 + cg*8;
        union { uint4 u; __nv_bfloat16 x[8]; } Uh, Ul;
        #pragma unroll
        for (int c = 0; c < 8; c++) {
            float v = fmaxf(acc[c][p], 0.f);
            __nv_bfloat16 hh = __float2bfloat16(v);
            Uh.x[c] = hh;
            Ul.x[c] = __float2bfloat16(v - __bfloat162float(hh));
        }
        *(uint4*)(out_hi + nb) = Uh.u;
        *(uint4*)(out_lo + nb) = Ul.u;
    }
}

// ===========================================================================
// conv3x3 64->64 (or 64->30 padded) via mma.sync bf16, 3-term split.
// CTA: 128 thr = 4 warps, each M=32 x N=64 (tile M=128, N=64).
// cp.async pipeline: B double-buffered per tap, A double-buffered per ky.
// ===========================================================================
#define RES_SMEM (2*33280 + 2*16384 + 512)

template<bool BNRELU, bool SKIP, bool OUTF32, int OSTRIDE>
__global__ __launch_bounds__(128) void res_conv_kernel(
    const __nv_bfloat16* __restrict__ in_hi, const __nv_bfloat16* __restrict__ in_lo,
    const __nv_bfloat16* __restrict__ Bg,
    const float* __restrict__ bng, const float* __restrict__ bnb,
    const float* __restrict__ bnm, const float* __restrict__ bnv,
    const __nv_bfloat16* __restrict__ sk_hi, const __nv_bfloat16* __restrict__ sk_lo,
    __nv_bfloat16* __restrict__ out_hi, __nv_bfloat16* __restrict__ out_lo,
    float* __restrict__ out_f32)
{
    extern __shared__ __align__(16) unsigned char dynsmem[];
    // layout: A0 A1 (130x256 each), B0 B1 (128x128 each), scales
    uint32_t aAbuf[2], aBbuf[2];
    {
        uint32_t base = smem_u32(dynsmem);
        aAbuf[0] = base;
        aAbuf[1] = base + 33280;
        aBbuf[0] = base + 66560;
        aBbuf[1] = base + 66560 + 16384;
    }
    float* s_sc = (float*)(dynsmem + 2*33280 + 2*16384);
    float* s_sh = s_sc + 64;

    const int tid  = threadIdx.x;
    const int wm   = tid >> 5;
    const int lane = tid & 31;
    const int w0   = blockIdx.x * 128;
    const int h    = blockIdx.y;
    const int b    = blockIdx.z;

    if (BNRELU && tid < 64) {
        float sc = bng[tid] * rsqrtf(bnv[tid] + 1e-5f);
        s_sc[tid] = sc;
        s_sh[tid] = bnb[tid] - bnm[tid] * sc;
    }

    // ---- staging lambdas ----
    auto stageA = [&](int ky, int sel) {
        const int hs = h + ky - 1;
        const bool hok = (hs >= 0) && (hs < HH);
        const int hc = hok ? hs : 0;
        for (int idx = tid; idx < 260; idx += 128) {
            int r = idx % 130;
            int half = idx / 130;
            int ws = w0 - 1 + r;
            bool ok = hok && (ws >= 0) && (ws < WW);
            int wc = (ws >= 0 && ws < WW) ? ws : 0;
            const char* src = (const char*)((half ? in_lo : in_hi)
                              + ((size_t)((b*HH + hc)*WW + wc))*64);
            uint32_t dstb = aAbuf[sel];
            #pragma unroll
            for (int j = 0; j < 8; j++)
                cpa16z(dstb + swzA(r, half*128 + j*16), src + j*16, ok);
        }
    };
    auto stageB = [&](int tap, int sel) {
        const __nv_bfloat16* bt = Bg + (size_t)tap*128*64;
        uint32_t dstb = aBbuf[sel];
        for (int idx = tid; idx < 1024; idx += 128) {
            int kr = idx >> 3, c = idx & 7;
            cpa16(dstb + swzB(kr*128 + c*16), bt + (size_t)kr*64 + c*8);
        }
    };

    float d[2][8][4];
    #pragma unroll
    for (int mf = 0; mf < 2; mf++)
        #pragma unroll
        for (int nf = 0; nf < 8; nf++)
            #pragma unroll
            for (int q = 0; q < 4; q++) d[mf][nf][q] = 0.f;

    // prologue: A(ky=0) + B(tap=0)
    stageA(0, 0);
    stageB(0, 0);
    CP_COMMIT();

    int t = 0;
    for (int ky = 0; ky < 3; ky++) {
        for (int kx = 0; kx < 3; kx++) {
            CP_WAIT0();
            __syncthreads();
            // prefetch next tap's B (and next ky's A at row start)
            if (t < 8) {
                stageB(t + 1, (t + 1) & 1);
                if (kx == 0 && ky < 2) stageA(ky + 1, (ky + 1) & 1);
                CP_COMMIT();
            }
            const uint32_t A_ = aAbuf[ky & 1];
            const uint32_t B_ = aBbuf[t & 1];

            // held A_yh fragments
            uint32_t Ah[4][2][4];
            #pragma unroll
            for (int j = 0; j < 4; j++)
                #pragma unroll
                for (int mf = 0; mf < 2; mf++) {
                    int arow = wm*32 + mf*16 + (lane & 15) + kx;
                    ldsm_x4(Ah[j][mf], A_ + swzA(arow, j*32 + (lane >> 4)*16));
                }
            // loop 1: wh shared between yh and yl
            #pragma unroll
            for (int j = 0; j < 4; j++) {
                uint32_t bw[4][4];
                const int krow = j*16 + (lane & 15);
                #pragma unroll
                for (int bq = 0; bq < 4; bq++)
                    ldsm_x4_t(bw[bq], B_ + swzB(krow*128 + bq*32 + (lane >> 4)*16));
                uint32_t Al[2][4];
                #pragma unroll
                for (int mf = 0; mf < 2; mf++) {
                    int arow = wm*32 + mf*16 + (lane & 15) + kx;
                    ldsm_x4(Al[mf], A_ + swzA(arow, 128 + j*32 + (lane >> 4)*16));
                }
                #pragma unroll
                for (int mf = 0; mf < 2; mf++)
                    #pragma unroll
                    for (int nf = 0; nf < 8; nf++)
                        mma_bf16(d[mf][nf], Ah[j][mf],
                                 bw[nf >> 1][(nf & 1)*2], bw[nf >> 1][(nf & 1)*2 + 1]);
                #pragma unroll
                for (int mf = 0; mf < 2; mf++)
                    #pragma unroll
                    for (int nf = 0; nf < 8; nf++)
                        mma_bf16(d[mf][nf], Al[mf],
                                 bw[nf >> 1][(nf & 1)*2], bw[nf >> 1][(nf & 1)*2 + 1]);
            }
            // loop 2: yh x wl
            #pragma unroll
            for (int j = 0; j < 4; j++) {
                uint32_t bl[4][4];
                const int krow = 64 + j*16 + (lane & 15);
                #pragma unroll
                for (int bq = 0; bq < 4; bq++)
                    ldsm_x4_t(bl[bq], B_ + swzB(krow*128 + bq*32 + (lane >> 4)*16));
                #pragma unroll
                for (int mf = 0; mf < 2; mf++)
                    #pragma unroll
                    for (int nf = 0; nf < 8; nf++)
                        mma_bf16(d[mf][nf], Ah[j][mf],
                                 bl[nf >> 1][(nf & 1)*2], bl[nf >> 1][(nf & 1)*2 + 1]);
            }
            t++;
        }
    }

    // ---- epilogue ----
    #pragma unroll
    for (int mf = 0; mf < 2; mf++) {
        #pragma unroll
        for (int rr = 0; rr < 2; rr++) {
            const int p = wm*32 + mf*16 + (lane >> 2) + rr*8;
            const int w = w0 + p;
            const size_t nbase = ((size_t)((b*HH + h)*WW + w))*64;
            #pragma unroll
            for (int nf = 0; nf < 8; nf++) {
                const int cout = nf*8 + (lane & 3)*2;
                float v0 = d[mf][nf][rr*2 + 0];
                float v1 = d[mf][nf][rr*2 + 1];
                if (BNRELU) {
                    v0 = fmaxf(v0 * s_sc[cout]     + s_sh[cout],     0.f);
                    v1 = fmaxf(v1 * s_sc[cout + 1] + s_sh[cout + 1], 0.f);
                }
                if (SKIP) {
                    uint32_t sh2 = *(const uint32_t*)(sk_hi + nbase + cout);
                    uint32_t sl2 = *(const uint32_t*)(sk_lo + nbase + cout);
                    v0 += __bfloat162float(__ushort_as_bfloat16((unsigned short)(sh2 & 0xFFFF)))
                        + __bfloat162float(__ushort_as_bfloat16((unsigned short)(sl2 & 0xFFFF)));
                    v1 += __bfloat162float(__ushort_as_bfloat16((unsigned short)(sh2 >> 16)))
                        + __bfloat162float(__ushort_as_bfloat16((unsigned short)(sl2 >> 16)));
                }
                if (OUTF32) {
                    if (OSTRIDE == 64 || cout < OSTRIDE)
                        out_f32[((size_t)(b*OSTRIDE + cout)*HH + h)*WW + w] = v0;
                    if (OSTRIDE == 64 || cout + 1 < OSTRIDE)
                        out_f32[((size_t)(b*OSTRIDE + cout + 1)*HH + h)*WW + w] = v1;
                } else {
                    __nv_bfloat16 h0 = __float2bfloat16(v0);
                    __nv_bfloat16 h1 = __float2bfloat16(v1);
                    __nv_bfloat16 l0 = __float2bfloat16(v0 - __bfloat162float(h0));
                    __nv_bfloat16 l1 = __float2bfloat16(v1 - __bfloat162float(h1));
                    uint32_t ph = (uint32_t)__bfloat16_as_ushort(h0)
                                | ((uint32_t)__bfloat16_as_ushort(h1) << 16);
                    uint32_t pl = (uint32_t)__bfloat16_as_ushort(l0)
                                | ((uint32_t)__bfloat16_as_ushort(l1) << 16);
                    *(uint32_t*)(out_hi + nbase + cout) = ph;
                    *(uint32_t*)(out_lo + nbase + cout) = pl;
                }
            }
        }
    }
}

// ===========================================================================
// Adaptive filtering
// ===========================================================================
__global__ __launch_bounds__(256) void filt_h_kernel(
    const float* __restrict__ filt, const float* __restrict__ base,
    float* __restrict__ fh)
{
    int idx = blockIdx.x * 256 + threadIdx.x;
    int w  = idx & 511;
    int h  = (idx >> 9) & 511;
    int bc = idx >> 18;
    int ch = bc % 3;
    int b  = bc / 3;

    const float* lp = filt + ((size_t)(b*30 + ch*10)*HH + h)*WW + w;
    float l[5];
    #pragma unroll
    for (int i = 0; i < 5; i++) l[i] = lp[(size_t)i*HWSZ];
    float m = fmaxf(fmaxf(fmaxf(l[0], l[1]), fmaxf(l[2], l[3])), l[4]);
    float e[5], s = 0.f;
    #pragma unroll
    for (int i = 0; i < 5; i++) { e[i] = __expf(l[i] - m); s += e[i]; }
    float inv = 1.f / s;

    const float* bp = base + (size_t)bc*HWSZ + w;
    float r = 0.f;
    #pragma unroll
    for (int i = 0; i < 5; i++) {
        int hh2 = h - 2 + i;
        float bv = (hh2 >= 0 && hh2 < HH) ? bp[(size_t)hh2*WW] : 0.f;
        r += bv * e[i] * inv;
    }
    fh[idx] = r;
}

__global__ __launch_bounds__(256) void filt_w_kernel(
    const float* __restrict__ filt, const float* __restrict__ fh,
    float* __restrict__ out)
{
    int idx = blockIdx.x * 256 + threadIdx.x;
    int w  = idx & 511;
    int h  = (idx >> 9) & 511;
    int bc = idx >> 18;
    int ch = bc % 3;
    int b  = bc / 3;

    const float* lp = filt + ((size_t)(b*30 + ch*10 + 5)*HH + h)*WW + w;
    float l[5];
    #pragma unroll
    for (int i = 0; i < 5; i++) l[i] = lp[(size_t)i*HWSZ];
    float m = fmaxf(fmaxf(fmaxf(l[0], l[1]), fmaxf(l[2], l[3])), l[4]);
    float e[5], s = 0.f;
    #pragma unroll
    for (int i = 0; i < 5; i++) { e[i] = __expf(l[i] - m); s += e[i]; }
    float inv = 1.f / s;

    const float* fp = fh + ((size_t)bc*HH + h)*WW;
    float r = 0.f;
    #pragma unroll
    for (int i = 0; i < 5; i++) {
        int ww2 = w - 2 + i;
        float fv = (ww2 >= 0 && ww2 < WW) ? fp[ww2] : 0.f;
        r += fv * e[i] * inv;
    }
    out[idx] = r;
}

// ===========================================================================
extern "C" void kernel_launch(void* const* d_in, const int* in_sizes, int n_in,
                              void* d_out, int out_size)
{
    const float* fm     = (const float*)d_in[0];
    const float* base   = (const float*)d_in[1];
    const float* wfirst = (const float*)d_in[2];
    const float* kbw1   = (const float*)d_in[3];
    const float* kbg1   = (const float*)d_in[4];
    const float* kbb1   = (const float*)d_in[5];
    const float* kbm1   = (const float*)d_in[6];
    const float* kbv1   = (const float*)d_in[7];
    const float* kbw2   = (const float*)d_in[8];
    const float* kbg2   = (const float*)d_in[9];
    const float* kbb2   = (const float*)d_in[10];
    const float* kbm2   = (const float*)d_in[11];
    const float* kbv2   = (const float*)d_in[12];
    const float* wlast  = (const float*)d_in[13];
    float* out = (float*)d_out;

    float *F, *FHp;
    __nv_bfloat16 *P0h, *P0l, *P1h, *P1l, *P2h, *P2l, *Bg;
    cudaGetSymbolAddress((void**)&F,   g_filt);
    cudaGetSymbolAddress((void**)&FHp, g_fh);
    cudaGetSymbolAddress((void**)&P0h, g_P0h);
    cudaGetSymbolAddress((void**)&P0l, g_P0l);
    cudaGetSymbolAddress((void**)&P1h, g_P1h);
    cudaGetSymbolAddress((void**)&P1l, g_P1l);
    cudaGetSymbolAddress((void**)&P2h, g_P2h);
    cudaGetSymbolAddress((void**)&P2l, g_P2l);
    cudaGetSymbolAddress((void**)&Bg,  g_Bg);

    cudaFuncSetAttribute(res_conv_kernel<true,false,false,64>,
                         cudaFuncAttributeMaxDynamicSharedMemorySize, RES_SMEM);
    cudaFuncSetAttribute(res_conv_kernel<true,true,false,64>,
                         cudaFuncAttributeMaxDynamicSharedMemorySize, RES_SMEM);
    cudaFuncSetAttribute(res_conv_kernel<false,false,true,30>,
                         cudaFuncAttributeMaxDynamicSharedMemorySize, RES_SMEM);

    // 1. weight prep (8 res convs + conv_last padded)
    prep_w_kernel<<<(9*9*128*64 + 255)/256, 256>>>(kbw1, kbw2, wlast, Bg);

    // 2. conv_first -> P0 pair
    dim3 g7(WW/16, HH/8, BATCH);
    conv7x7_kernel<<<g7, 256>>>(fm, wfirst, P0h, P0l);

    // 3. residual blocks
    dim3 gr(WW/128, HH, BATCH);
    const size_t SL = (size_t)9*128*64;
    __nv_bfloat16 *yh = P0h, *yl = P0l;
    __nv_bfloat16 *alt_h = P2h, *alt_l = P2l;
    for (int r = 0; r < 4; r++) {
        res_conv_kernel<true,false,false,64><<<gr, 128, RES_SMEM>>>(
            yh, yl, Bg + (size_t)(r*2+0)*SL,
            kbg1 + r*64, kbb1 + r*64, kbm1 + r*64, kbv1 + r*64,
            nullptr, nullptr, P1h, P1l, nullptr);
        res_conv_kernel<true,true,false,64><<<gr, 128, RES_SMEM>>>(
            P1h, P1l, Bg + (size_t)(r*2+1)*SL,
            kbg2 + r*64, kbb2 + r*64, kbm2 + r*64, kbv2 + r*64,
            yh, yl, alt_h, alt_l, nullptr);
        __nv_bfloat16* th = yh; __nv_bfloat16* tl = yl;
        yh = alt_h; yl = alt_l;
        alt_h = th; alt_l = tl;
    }

    // 4. conv_last via MMA (couts padded 30->64, stride-30 fp32 NCHW epilogue)
    res_conv_kernel<false,false,true,30><<<gr, 128, RES_SMEM>>>(
        yh, yl, Bg + (size_t)8*SL,
        nullptr, nullptr, nullptr, nullptr,
        nullptr, nullptr, nullptr, nullptr, F);

    // 5. adaptive filtering
    int npix = BATCH*3*HWSZ;
    filt_h_kernel<<<npix/256, 256>>>(F, base, FHp);
    filt_w_kernel<<<npix/256, 256>>>(F, FHp, out);
}

// round 11
// speedup vs baseline: 3.4392x; 1.0897x over previous
#include <cuda_runtime.h>
#include <cuda_bf16.h>
#include <cstdint>

#define HH 512
#define WW 512
#define BATCH 2
#define HWSZ (HH*WW)

// ===========================================================================
// Warp-MMA + cp.async helpers (family-compatible)
// ===========================================================================
__device__ __forceinline__ uint32_t smem_u32(const void* p) {
    uint32_t a;
    asm("{ .reg .u64 t; cvta.to.shared.u64 t, %1; cvt.u32.u64 %0, t; }"
        : "=r"(a) : "l"(p));
    return a;
}
__device__ __forceinline__ void ldsm_x4(uint32_t* r, uint32_t addr) {
    asm volatile("ldmatrix.sync.aligned.m8n8.x4.shared.b16 {%0,%1,%2,%3}, [%4];"
        : "=r"(r[0]), "=r"(r[1]), "=r"(r[2]), "=r"(r[3]) : "r"(addr));
}
__device__ __forceinline__ void ldsm_x4_t(uint32_t* r, uint32_t addr) {
    asm volatile("ldmatrix.sync.aligned.m8n8.x4.trans.shared.b16 {%0,%1,%2,%3}, [%4];"
        : "=r"(r[0]), "=r"(r[1]), "=r"(r[2]), "=r"(r[3]) : "r"(addr));
}
__device__ __forceinline__ void mma_bf16(float* d, const uint32_t* a,
                                         uint32_t b0, uint32_t b1) {
    asm volatile("mma.sync.aligned.m16n8k16.row.col.f32.bf16.bf16.f32 "
        "{%0,%1,%2,%3}, {%4,%5,%6,%7}, {%8,%9}, {%0,%1,%2,%3};"
        : "+f"(d[0]), "+f"(d[1]), "+f"(d[2]), "+f"(d[3])
        : "r"(a[0]), "r"(a[1]), "r"(a[2]), "r"(a[3]), "r"(b0), "r"(b1));
}
__device__ __forceinline__ void cpa16(uint32_t dst, const void* src) {
    asm volatile("cp.async.cg.shared.global [%0], [%1], 16;"
                 :: "r"(dst), "l"(src) : "memory");
}
__device__ __forceinline__ void cpa16z(uint32_t dst, const void* src, int ok) {
    asm volatile("cp.async.cg.shared.global [%0], [%1], 16, %2;"
                 :: "r"(dst), "l"(src), "r"(ok ? 16 : 0) : "memory");
}
#define CP_COMMIT() asm volatile("cp.async.commit_group;" ::: "memory")
#define CP_WAIT0()  asm volatile("cp.async.wait_group 0;" ::: "memory")

// XOR swizzle for 128B-row tiles (B smem)
__device__ __forceinline__ uint32_t swzB(uint32_t off) {
    return off ^ ((off >> 3) & 0x70);
}
// swizzle for 256B-row tiles (A smem): chunk' = (c&8) | ((c^row)&7)
__device__ __forceinline__ uint32_t swzA(int row, int kbyte) {
    int c = kbyte >> 4;
    int cs = (c & 8) | ((c ^ row) & 7);
    return (uint32_t)(row * 256 + (cs << 4));
}

// ===========================================================================
// Persistent scratch
// ===========================================================================
__device__ float g_filt[(size_t)BATCH*30*HWSZ];
__device__ float g_fh[(size_t)BATCH*3*HWSZ];
// NHWC bf16 activation pairs [b][h][w][c]
__device__ __nv_bfloat16 g_P0h[(size_t)BATCH*HWSZ*64];
__device__ __nv_bfloat16 g_P0l[(size_t)BATCH*HWSZ*64];
__device__ __nv_bfloat16 g_P1h[(size_t)BATCH*HWSZ*64];
__device__ __nv_bfloat16 g_P1l[(size_t)BATCH*HWSZ*64];
__device__ __nv_bfloat16 g_P2h[(size_t)BATCH*HWSZ*64];
__device__ __nv_bfloat16 g_P2l[(size_t)BATCH*HWSZ*64];
// prepped weights: 9 sections (8 res convs + conv_last padded) x [tap][k=128][cout=64]
// k: [wh(64) | wl(64)] over cin
__device__ __nv_bfloat16 g_Bg[(size_t)9*9*128*64];

// ===========================================================================
// Weight prep
// ===========================================================================
__global__ void prep_w_kernel(const float* __restrict__ w1, const float* __restrict__ w2,
                              const float* __restrict__ wlast,
                              __nv_bfloat16* __restrict__ Bg)
{
    int idx = blockIdx.x * 256 + threadIdx.x;
    if (idx >= 9*9*128*64) return;
    int co  = idx & 63;
    int k   = (idx >> 6) % 128;
    int tap = (idx >> 6) / 128 % 9;
    int rc  = idx / (128*64*9);
    int cin = (k < 64) ? k : (k - 64);
    int ky = tap / 3, kx = tap % 3;
    float v;
    if (rc < 8) {
        int conv = rc & 1, r = rc >> 1;
        const float* src = conv ? w2 : w1;
        v = src[(((r*64 + co)*64 + cin)*3 + ky)*3 + kx];
    } else {
        v = (co < 30) ? wlast[((co*64 + cin)*3 + ky)*3 + kx] : 0.f;
    }
    __nv_bfloat16 h = __float2bfloat16(v);
    if (k < 64) Bg[idx] = h;
    else        Bg[idx] = __float2bfloat16(v - __bfloat162float(h));
}

// ===========================================================================
// conv 7x7, Cin=6 -> 64, pad 3, ReLU. Scalar fp32; outputs NHWC bf16 hi/lo.
// ===========================================================================
__global__ __launch_bounds__(256) void conv7x7_kernel(
    const float* __restrict__ in, const float* __restrict__ wt,
    __nv_bfloat16* __restrict__ out_hi, __nv_bfloat16* __restrict__ out_lo)
{
    __shared__ float s_in[6][14][24];
    __shared__ float s_w[64][7][8];

    const int tid  = threadIdx.x;
    const int cg   = tid >> 5;
    const int slot = tid & 31;
    const int pr   = slot >> 2;
    const int pc4  = (slot & 3) * 4;
    const int h0   = blockIdx.y * 8;
    const int w0   = blockIdx.x * 16;
    const int b    = blockIdx.z;

    for (int i = tid; i < 6*14*22; i += 256) {
        int ci = i / (14*22);
        int r  = (i / 22) % 14;
        int c  = i % 22;
        int gh = h0 - 3 + r;
        int gw = w0 - 3 + c;
        float v = 0.f;
        if (gh >= 0 && gh < HH && gw >= 0 && gw < WW)
            v = in[((b*6 + ci)*HH + gh)*WW + gw];
        s_in[ci][r][c] = v;
    }

    float acc[8][4];
    #pragma unroll
    for (int c = 0; c < 8; c++)
        #pragma unroll
        for (int p = 0; p < 4; p++) acc[c][p] = 0.f;

    for (int cin = 0; cin < 6; cin++) {
        __syncthreads();
        for (int i = tid; i < 64*49; i += 256) {
            int co = i / 49, k = i % 49;
            s_w[co][k/7][k%7] = wt[(co*6 + cin)*49 + k];
        }
        __syncthreads();
        #pragma unroll 1
        for (int ky = 0; ky < 7; ky++) {
            float xr[10];
            const float* rp = &s_in[cin][pr + ky][pc4];
            #pragma unroll
            for (int j = 0; j < 10; j++) xr[j] = rp[j];
            #pragma unroll
            for (int c = 0; c < 8; c++) {
                const float* wp = &s_w[cg*8 + c][ky][0];
                float wv[7];
                #pragma unroll
                for (int q = 0; q < 7; q++) wv[q] = wp[q];
                #pragma unroll
                for (int p = 0; p < 4; p++) {
                    float s = acc[c][p];
                    #pragma unroll
                    for (int q = 0; q < 7; q++) s += xr[p+q] * wv[q];
                    acc[c][p] = s;
                }
            }
        }
    }

    const int h = h0 + pr;
    #pragma unroll
    for (int p = 0; p < 4; p++) {
        int w = w0 + pc4 + p;
        size_t nb = ((size_t)((b*HH + h)*WW + w))*64 + cg*8;
        union { uint4 u; __nv_bfloat16 x[8]; } Uh, Ul;
        #pragma unroll
        for (int c = 0; c < 8; c++) {
            float v = fmaxf(acc[c][p], 0.f);
            __nv_bfloat16 hh = __float2bfloat16(v);
            Uh.x[c] = hh;
            Ul.x[c] = __float2bfloat16(v - __bfloat162float(hh));
        }
        *(uint4*)(out_hi + nb) = Uh.u;
        *(uint4*)(out_lo + nb) = Ul.u;
    }
}

// ===========================================================================
// conv3x3 64->64 (or 64->30 padded) via mma.sync bf16, 3-term split.
// CTA: 128 thr = 4 warps, each M=32 x N=64 (tile M=128, N=64).
// A single-buffered (re-staged per ky), B double-buffered per tap.
// Per-j fused passes keep register pressure low -> 3 CTAs/SM.
// ===========================================================================
#define RES_SMEM (33280 + 2*16384 + 512)

template<bool BNRELU, bool SKIP, bool OUTF32, int OSTRIDE>
__global__ __launch_bounds__(128, 3) void res_conv_kernel(
    const __nv_bfloat16* __restrict__ in_hi, const __nv_bfloat16* __restrict__ in_lo,
    const __nv_bfloat16* __restrict__ Bg,
    const float* __restrict__ bng, const float* __restrict__ bnb,
    const float* __restrict__ bnm, const float* __restrict__ bnv,
    const __nv_bfloat16* __restrict__ sk_hi, const __nv_bfloat16* __restrict__ sk_lo,
    __nv_bfloat16* __restrict__ out_hi, __nv_bfloat16* __restrict__ out_lo,
    float* __restrict__ out_f32)
{
    extern __shared__ __align__(16) unsigned char dynsmem[];
    // layout: A (130x256), B0 B1 (128x128 each), scales
    uint32_t aA, aBbuf[2];
    {
        uint32_t base = smem_u32(dynsmem);
        aA = base;
        aBbuf[0] = base + 33280;
        aBbuf[1] = base + 33280 + 16384;
    }
    float* s_sc = (float*)(dynsmem + 33280 + 2*16384);
    float* s_sh = s_sc + 64;

    const int tid  = threadIdx.x;
    const int wm   = tid >> 5;
    const int lane = tid & 31;
    const int w0   = blockIdx.x * 128;
    const int h    = blockIdx.y;
    const int b    = blockIdx.z;

    if (BNRELU && tid < 64) {
        float sc = bng[tid] * rsqrtf(bnv[tid] + 1e-5f);
        s_sc[tid] = sc;
        s_sh[tid] = bnb[tid] - bnm[tid] * sc;
    }

    // ---- staging lambdas ----
    auto stageA = [&](int ky) {
        const int hs = h + ky - 1;
        const bool hok = (hs >= 0) && (hs < HH);
        const int hc = hok ? hs : 0;
        for (int idx = tid; idx < 260; idx += 128) {
            int r = idx % 130;
            int half = idx / 130;
            int ws = w0 - 1 + r;
            bool ok = hok && (ws >= 0) && (ws < WW);
            int wc = (ws >= 0 && ws < WW) ? ws : 0;
            const char* src = (const char*)((half ? in_lo : in_hi)
                              + ((size_t)((b*HH + hc)*WW + wc))*64);
            #pragma unroll
            for (int j = 0; j < 8; j++)
                cpa16z(aA + swzA(r, half*128 + j*16), src + j*16, ok);
        }
    };
    auto stageB = [&](int tap, int sel) {
        const __nv_bfloat16* bt = Bg + (size_t)tap*128*64;
        uint32_t dstb = aBbuf[sel];
        for (int idx = tid; idx < 1024; idx += 128) {
            int kr = idx >> 3, c = idx & 7;
            cpa16(dstb + swzB(kr*128 + c*16), bt + (size_t)kr*64 + c*8);
        }
    };

    float d[2][8][4];
    #pragma unroll
    for (int mf = 0; mf < 2; mf++)
        #pragma unroll
        for (int nf = 0; nf < 8; nf++)
            #pragma unroll
            for (int q = 0; q < 4; q++) d[mf][nf][q] = 0.f;

    // prologue: A(ky=0) + B(tap=0)
    stageA(0);
    stageB(0, 0);
    CP_COMMIT();

    int t = 0;
    for (int ky = 0; ky < 3; ky++) {
        for (int kx = 0; kx < 3; kx++) {
            CP_WAIT0();
            __syncthreads();
            if (t < 8) {                       // prefetch next tap's B
                stageB(t + 1, (t + 1) & 1);
                CP_COMMIT();
            }
            const uint32_t B_ = aBbuf[t & 1];

            #pragma unroll
            for (int j = 0; j < 4; j++) {
                uint32_t Ah[2][4], Al[2][4];
                #pragma unroll
                for (int mf = 0; mf < 2; mf++) {
                    int arow = wm*32 + mf*16 + (lane & 15) + kx;
                    ldsm_x4(Ah[mf], aA + swzA(arow, j*32 + (lane >> 4)*16));
                    ldsm_x4(Al[mf], aA + swzA(arow, 128 + j*32 + (lane >> 4)*16));
                }
                uint32_t bw[4][4], bl[4][4];
                const int krow  = j*16 + (lane & 15);
                #pragma unroll
                for (int bq = 0; bq < 4; bq++) {
                    ldsm_x4_t(bw[bq], B_ + swzB(krow*128 + bq*32 + (lane >> 4)*16));
                    ldsm_x4_t(bl[bq], B_ + swzB((krow + 64)*128 + bq*32 + (lane >> 4)*16));
                }
                #pragma unroll
                for (int mf = 0; mf < 2; mf++)
                    #pragma unroll
                    for (int nf = 0; nf < 8; nf++)
                        mma_bf16(d[mf][nf], Ah[mf],
                                 bw[nf >> 1][(nf & 1)*2], bw[nf >> 1][(nf & 1)*2 + 1]);
                #pragma unroll
                for (int mf = 0; mf < 2; mf++)
                    #pragma unroll
                    for (int nf = 0; nf < 8; nf++)
                        mma_bf16(d[mf][nf], Al[mf],
                                 bw[nf >> 1][(nf & 1)*2], bw[nf >> 1][(nf & 1)*2 + 1]);
                #pragma unroll
                for (int mf = 0; mf < 2; mf++)
                    #pragma unroll
                    for (int nf = 0; nf < 8; nf++)
                        mma_bf16(d[mf][nf], Ah[mf],
                                 bl[nf >> 1][(nf & 1)*2], bl[nf >> 1][(nf & 1)*2 + 1]);
            }
            t++;
        }
        if (ky < 2) {                          // re-stage single A buffer
            __syncthreads();                   // all A reads of this ky done
            stageA(ky + 1);
            CP_COMMIT();
        }
    }

    // ---- epilogue ----
    #pragma unroll
    for (int mf = 0; mf < 2; mf++) {
        #pragma unroll
        for (int rr = 0; rr < 2; rr++) {
            const int p = wm*32 + mf*16 + (lane >> 2) + rr*8;
            const int w = w0 + p;
            const size_t nbase = ((size_t)((b*HH + h)*WW + w))*64;
            #pragma unroll
            for (int nf = 0; nf < 8; nf++) {
                const int cout = nf*8 + (lane & 3)*2;
                float v0 = d[mf][nf][rr*2 + 0];
                float v1 = d[mf][nf][rr*2 + 1];
                if (BNRELU) {
                    v0 = fmaxf(v0 * s_sc[cout]     + s_sh[cout],     0.f);
                    v1 = fmaxf(v1 * s_sc[cout + 1] + s_sh[cout + 1], 0.f);
                }
                if (SKIP) {
                    uint32_t sh2 = *(const uint32_t*)(sk_hi + nbase + cout);
                    uint32_t sl2 = *(const uint32_t*)(sk_lo + nbase + cout);
                    v0 += __bfloat162float(__ushort_as_bfloat16((unsigned short)(sh2 & 0xFFFF)))
                        + __bfloat162float(__ushort_as_bfloat16((unsigned short)(sl2 & 0xFFFF)));
                    v1 += __bfloat162float(__ushort_as_bfloat16((unsigned short)(sh2 >> 16)))
                        + __bfloat162float(__ushort_as_bfloat16((unsigned short)(sl2 >> 16)));
                }
                if (OUTF32) {
                    if (OSTRIDE == 64 || cout < OSTRIDE)
                        out_f32[((size_t)(b*OSTRIDE + cout)*HH + h)*WW + w] = v0;
                    if (OSTRIDE == 64 || cout + 1 < OSTRIDE)
                        out_f32[((size_t)(b*OSTRIDE + cout + 1)*HH + h)*WW + w] = v1;
                } else {
                    __nv_bfloat16 h0 = __float2bfloat16(v0);
                    __nv_bfloat16 h1 = __float2bfloat16(v1);
                    __nv_bfloat16 l0 = __float2bfloat16(v0 - __bfloat162float(h0));
                    __nv_bfloat16 l1 = __float2bfloat16(v1 - __bfloat162float(h1));
                    uint32_t ph = (uint32_t)__bfloat16_as_ushort(h0)
                                | ((uint32_t)__bfloat16_as_ushort(h1) << 16);
                    uint32_t pl = (uint32_t)__bfloat16_as_ushort(l0)
                                | ((uint32_t)__bfloat16_as_ushort(l1) << 16);
                    *(uint32_t*)(out_hi + nbase + cout) = ph;
                    *(uint32_t*)(out_lo + nbase + cout) = pl;
                }
            }
        }
    }
}

// ===========================================================================
// Adaptive filtering
// ===========================================================================
__global__ __launch_bounds__(256) void filt_h_kernel(
    const float* __restrict__ filt, const float* __restrict__ base,
    float* __restrict__ fh)
{
    int idx = blockIdx.x * 256 + threadIdx.x;
    int w  = idx & 511;
    int h  = (idx >> 9) & 511;
    int bc = idx >> 18;
    int ch = bc % 3;
    int b  = bc / 3;

    const float* lp = filt + ((size_t)(b*30 + ch*10)*HH + h)*WW + w;
    float l[5];
    #pragma unroll
    for (int i = 0; i < 5; i++) l[i] = lp[(size_t)i*HWSZ];
    float m = fmaxf(fmaxf(fmaxf(l[0], l[1]), fmaxf(l[2], l[3])), l[4]);
    float e[5], s = 0.f;
    #pragma unroll
    for (int i = 0; i < 5; i++) { e[i] = __expf(l[i] - m); s += e[i]; }
    float inv = 1.f / s;

    const float* bp = base + (size_t)bc*HWSZ + w;
    float r = 0.f;
    #pragma unroll
    for (int i = 0; i < 5; i++) {
        int hh2 = h - 2 + i;
        float bv = (hh2 >= 0 && hh2 < HH) ? bp[(size_t)hh2*WW] : 0.f;
        r += bv * e[i] * inv;
    }
    fh[idx] = r;
}

__global__ __launch_bounds__(256) void filt_w_kernel(
    const float* __restrict__ filt, const float* __restrict__ fh,
    float* __restrict__ out)
{
    int idx = blockIdx.x * 256 + threadIdx.x;
    int w  = idx & 511;
    int h  = (idx >> 9) & 511;
    int bc = idx >> 18;
    int ch = bc % 3;
    int b  = bc / 3;

    const float* lp = filt + ((size_t)(b*30 + ch*10 + 5)*HH + h)*WW + w;
    float l[5];
    #pragma unroll
    for (int i = 0; i < 5; i++) l[i] = lp[(size_t)i*HWSZ];
    float m = fmaxf(fmaxf(fmaxf(l[0], l[1]), fmaxf(l[2], l[3])), l[4]);
    float e[5], s = 0.f;
    #pragma unroll
    for (int i = 0; i < 5; i++) { e[i] = __expf(l[i] - m); s += e[i]; }
    float inv = 1.f / s;

    const float* fp = fh + ((size_t)bc*HH + h)*WW;
    float r = 0.f;
    #pragma unroll
    for (int i = 0; i < 5; i++) {
        int ww2 = w - 2 + i;
        float fv = (ww2 >= 0 && ww2 < WW) ? fp[ww2] : 0.f;
        r += fv * e[i] * inv;
    }
    out[idx] = r;
}

// ===========================================================================
extern "C" void kernel_launch(void* const* d_in, const int* in_sizes, int n_in,
                              void* d_out, int out_size)
{
    const float* fm     = (const float*)d_in[0];
    const float* base   = (const float*)d_in[1];
    const float* wfirst = (const float*)d_in[2];
    const float* kbw1   = (const float*)d_in[3];
    const float* kbg1   = (const float*)d_in[4];
    const float* kbb1   = (const float*)d_in[5];
    const float* kbm1   = (const float*)d_in[6];
    const float* kbv1   = (const float*)d_in[7];
    const float* kbw2   = (const float*)d_in[8];
    const float* kbg2   = (const float*)d_in[9];
    const float* kbb2   = (const float*)d_in[10];
    const float* kbm2   = (const float*)d_in[11];
    const float* kbv2   = (const float*)d_in[12];
    const float* wlast  = (const float*)d_in[13];
    float* out = (float*)d_out;

    float *F, *FHp;
    __nv_bfloat16 *P0h, *P0l, *P1h, *P1l, *P2h, *P2l, *Bg;
    cudaGetSymbolAddress((void**)&F,   g_filt);
    cudaGetSymbolAddress((void**)&FHp, g_fh);
    cudaGetSymbolAddress((void**)&P0h, g_P0h);
    cudaGetSymbolAddress((void**)&P0l, g_P0l);
    cudaGetSymbolAddress((void**)&P1h, g_P1h);
    cudaGetSymbolAddress((void**)&P1l, g_P1l);
    cudaGetSymbolAddress((void**)&P2h, g_P2h);
    cudaGetSymbolAddress((void**)&P2l, g_P2l);
    cudaGetSymbolAddress((void**)&Bg,  g_Bg);

    cudaFuncSetAttribute(res_conv_kernel<true,false,false,64>,
                         cudaFuncAttributeMaxDynamicSharedMemorySize, RES_SMEM);
    cudaFuncSetAttribute(res_conv_kernel<true,true,false,64>,
                         cudaFuncAttributeMaxDynamicSharedMemorySize, RES_SMEM);
    cudaFuncSetAttribute(res_conv_kernel<false,false,true,30>,
                         cudaFuncAttributeMaxDynamicSharedMemorySize, RES_SMEM);

    // 1. weight prep (8 res convs + conv_last padded)
    prep_w_kernel<<<(9*9*128*64 + 255)/256, 256>>>(kbw1, kbw2, wlast, Bg);

    // 2. conv_first -> P0 pair
    dim3 g7(WW/16, HH/8, BATCH);
    conv7x7_kernel<<<g7, 256>>>(fm, wfirst, P0h, P0l);

    // 3. residual blocks
    dim3 gr(WW/128, HH, BATCH);
    const size_t SL = (size_t)9*128*64;
    __nv_bfloat16 *yh = P0h, *yl = P0l;
    __nv_bfloat16 *alt_h = P2h, *alt_l = P2l;
    for (int r = 0; r < 4; r++) {
        res_conv_kernel<true,false,false,64><<<gr, 128, RES_SMEM>>>(
            yh, yl, Bg + (size_t)(r*2+0)*SL,
            kbg1 + r*64, kbb1 + r*64, kbm1 + r*64, kbv1 + r*64,
            nullptr, nullptr, P1h, P1l, nullptr);
        res_conv_kernel<true,true,false,64><<<gr, 128, RES_SMEM>>>(
            P1h, P1l, Bg + (size_t)(r*2+1)*SL,
            kbg2 + r*64, kbb2 + r*64, kbm2 + r*64, kbv2 + r*64,
            yh, yl, alt_h, alt_l, nullptr);
        __nv_bfloat16* th = yh; __nv_bfloat16* tl = yl;
        yh = alt_h; yl = alt_l;
        alt_h = th; alt_l = tl;
    }

    // 4. conv_last via MMA (couts padded 30->64, stride-30 fp32 NCHW epilogue)
    res_conv_kernel<false,false,true,30><<<gr, 128, RES_SMEM>>>(
        yh, yl, Bg + (size_t)8*SL,
        nullptr, nullptr, nullptr, nullptr,
        nullptr, nullptr, nullptr, nullptr, F);

    // 5. adaptive filtering
    int npix = BATCH*3*HWSZ;
    filt_h_kernel<<<npix/256, 256>>>(F, base, FHp);
    filt_w_kernel<<<npix/256, 256>>>(F, FHp, out);
}

// round 14
// speedup vs baseline: 3.5324x; 1.0271x over previous
#include <cuda_runtime.h>
#include <cuda_bf16.h>
#include <cstdint>

#define HH 512
#define WW 512
#define BATCH 2
#define HWSZ (HH*WW)

// ===========================================================================
// Warp-MMA + cp.async helpers (family-compatible)
// ===========================================================================
__device__ __forceinline__ uint32_t smem_u32(const void* p) {
    uint32_t a;
    asm("{ .reg .u64 t; cvta.to.shared.u64 t, %1; cvt.u32.u64 %0, t; }"
        : "=r"(a) : "l"(p));
    return a;
}
__device__ __forceinline__ void ldsm_x4(uint32_t* r, uint32_t addr) {
    asm volatile("ldmatrix.sync.aligned.m8n8.x4.shared.b16 {%0,%1,%2,%3}, [%4];"
        : "=r"(r[0]), "=r"(r[1]), "=r"(r[2]), "=r"(r[3]) : "r"(addr));
}
__device__ __forceinline__ void mma_bf16(float* d, const uint32_t* a,
                                         uint32_t b0, uint32_t b1) {
    asm volatile("mma.sync.aligned.m16n8k16.row.col.f32.bf16.bf16.f32 "
        "{%0,%1,%2,%3}, {%4,%5,%6,%7}, {%8,%9}, {%0,%1,%2,%3};"
        : "+f"(d[0]), "+f"(d[1]), "+f"(d[2]), "+f"(d[3])
        : "r"(a[0]), "r"(a[1]), "r"(a[2]), "r"(a[3]), "r"(b0), "r"(b1));
}
__device__ __forceinline__ void cpa16z(uint32_t dst, const void* src, int ok) {
    asm volatile("cp.async.cg.shared.global [%0], [%1], 16, %2;"
                 :: "r"(dst), "l"(src), "r"(ok ? 16 : 0) : "memory");
}
#define CP_COMMIT() asm volatile("cp.async.commit_group;" ::: "memory")
#define CP_WAIT0()  asm volatile("cp.async.wait_group 0;" ::: "memory")

// swizzle for 256B-row tiles (A smem): chunk' = (c&8) | ((c^row)&7)
__device__ __forceinline__ uint32_t swzA(int row, int kbyte) {
    int c = kbyte >> 4;
    int cs = (c & 8) | ((c ^ row) & 7);
    return (uint32_t)(row * 256 + (cs << 4));
}

// ===========================================================================
// Persistent scratch
// ===========================================================================
__device__ float g_filt[(size_t)BATCH*30*HWSZ];
__device__ float g_fh[(size_t)BATCH*3*HWSZ];
// NHWC bf16 activation pairs [b][h][w][c]
__device__ __nv_bfloat16 g_P0h[(size_t)BATCH*HWSZ*64];
__device__ __nv_bfloat16 g_P0l[(size_t)BATCH*HWSZ*64];
__device__ __nv_bfloat16 g_P1h[(size_t)BATCH*HWSZ*64];
__device__ __nv_bfloat16 g_P1l[(size_t)BATCH*HWSZ*64];
__device__ __nv_bfloat16 g_P2h[(size_t)BATCH*HWSZ*64];
__device__ __nv_bfloat16 g_P2l[(size_t)BATCH*HWSZ*64];
// Pre-shuffled B fragments: [sec=9][tap=9][j=4][term=2][g=4][lane=32] uint4.
// strides (uint4): lane=1, g=32, term=128, j=256, tap=1024, sec=9216
__device__ uint4 g_FragB[(size_t)9*9*4*2*4*32];

// ===========================================================================
// Weight prep: build mma-ready B fragments (hi/lo split) from raw fp32 weights
// ===========================================================================
__global__ void prep_w_kernel(const float* __restrict__ w1, const float* __restrict__ w2,
                              const float* __restrict__ wlast,
                              uint4* __restrict__ Fb)
{
    int idx = blockIdx.x * 256 + threadIdx.x;
    if (idx >= 9*9216) return;
    int lane = idx & 31;
    int g    = (idx >> 5) & 3;
    int term = (idx >> 7) & 1;
    int j    = (idx >> 8) & 3;
    int tap  = (idx >> 10) % 9;
    int sec  = idx / 9216;
    int ky = tap / 3, kx = tap % 3;
    int nl = lane >> 2, kk = (lane & 3) * 2;
    int n0 = g*16 + nl, n1 = n0 + 8;
    int k0 = j*16 + kk;

    auto enc = [&](int co, int ci) -> uint32_t {
        float v;
        if (sec < 8) {
            int conv = sec & 1, r = sec >> 1;
            const float* s = conv ? w2 : w1;
            v = s[(((r*64 + co)*64 + ci)*3 + ky)*3 + kx];
        } else {
            v = (co < 30) ? wlast[((co*64 + ci)*3 + ky)*3 + kx] : 0.f;
        }
        __nv_bfloat16 h = __float2bfloat16(v);
        if (term) h = __float2bfloat16(v - __bfloat162float(h));
        return (uint32_t)__bfloat16_as_ushort(h);
    };
    uint4 o;
    o.x = enc(n0, k0)     | (enc(n0, k0 + 1) << 16);
    o.y = enc(n0, k0 + 8) | (enc(n0, k0 + 9) << 16);
    o.z = enc(n1, k0)     | (enc(n1, k0 + 1) << 16);
    o.w = enc(n1, k0 + 8) | (enc(n1, k0 + 9) << 16);
    Fb[idx] = o;
}

// ===========================================================================
// conv 7x7, Cin=6 -> 64, pad 3, ReLU. Scalar fp32; outputs NHWC bf16 hi/lo.
// ===========================================================================
__global__ __launch_bounds__(256) void conv7x7_kernel(
    const float* __restrict__ in, const float* __restrict__ wt,
    __nv_bfloat16* __restrict__ out_hi, __nv_bfloat16* __restrict__ out_lo)
{
    __shared__ float s_in[6][14][24];
    __shared__ float s_w[64][7][8];

    const int tid  = threadIdx.x;
    const int cg   = tid >> 5;
    const int slot = tid & 31;
    const int pr   = slot >> 2;
    const int pc4  = (slot & 3) * 4;
    const int h0   = blockIdx.y * 8;
    const int w0   = blockIdx.x * 16;
    const int b    = blockIdx.z;

    for (int i = tid; i < 6*14*22; i += 256) {
        int ci = i / (14*22);
        int r  = (i / 22) % 14;
        int c  = i % 22;
        int gh = h0 - 3 + r;
        int gw = w0 - 3 + c;
        float v = 0.f;
        if (gh >= 0 && gh < HH && gw >= 0 && gw < WW)
            v = in[((b*6 + ci)*HH + gh)*WW + gw];
        s_in[ci][r][c] = v;
    }

    float acc[8][4];
    #pragma unroll
    for (int c = 0; c < 8; c++)
        #pragma unroll
        for (int p = 0; p < 4; p++) acc[c][p] = 0.f;

    for (int cin = 0; cin < 6; cin++) {
        __syncthreads();
        for (int i = tid; i < 64*49; i += 256) {
            int co = i / 49, k = i % 49;
            s_w[co][k/7][k%7] = wt[(co*6 + cin)*49 + k];
        }
        __syncthreads();
        #pragma unroll 1
        for (int ky = 0; ky < 7; ky++) {
            float xr[10];
            const float* rp = &s_in[cin][pr + ky][pc4];
            #pragma unroll
            for (int j = 0; j < 10; j++) xr[j] = rp[j];
            #pragma unroll
            for (int c = 0; c < 8; c++) {
                const float* wp = &s_w[cg*8 + c][ky][0];
                float wv[7];
                #pragma unroll
                for (int q = 0; q < 7; q++) wv[q] = wp[q];
                #pragma unroll
                for (int p = 0; p < 4; p++) {
                    float s = acc[c][p];
                    #pragma unroll
                    for (int q = 0; q < 7; q++) s += xr[p+q] * wv[q];
                    acc[c][p] = s;
                }
            }
        }
    }

    const int h = h0 + pr;
    #pragma unroll
    for (int p = 0; p < 4; p++) {
        int w = w0 + pc4 + p;
        size_t nb = ((size_t)((b*HH + h)*WW + w))*64 + cg*8;
        union { uint4 u; __nv_bfloat16 x[8]; } Uh, Ul;
        #pragma unroll
        for (int c = 0; c < 8; c++) {
            float v = fmaxf(acc[c][p], 0.f);
            __nv_bfloat16 hh = __float2bfloat16(v);
            Uh.x[c] = hh;
            Ul.x[c] = __float2bfloat16(v - __bfloat162float(hh));
        }
        *(uint4*)(out_hi + nb) = Uh.u;
        *(uint4*)(out_lo + nb) = Ul.u;
    }
}

// ===========================================================================
// conv3x3 64->64 (or 64->30 padded) via mma.sync bf16, 3-term split.
// CTA: 128 thr = 4 warps, each M=32 x N=64 (tile M=128, N=64).
// A double-buffered per ky via cp.async; B fragments via LDG.128 from
// pre-shuffled g_FragB (broadcast across warps). NO per-tap syncs.
// ===========================================================================
#define RES_SMEM (2*33280 + 512)

template<bool BNRELU, bool SKIP, bool OUTF32, int OSTRIDE>
__global__ __launch_bounds__(128, 3) void res_conv_kernel(
    const __nv_bfloat16* __restrict__ in_hi, const __nv_bfloat16* __restrict__ in_lo,
    const uint4* __restrict__ Fb,
    const float* __restrict__ bng, const float* __restrict__ bnb,
    const float* __restrict__ bnm, const float* __restrict__ bnv,
    const __nv_bfloat16* __restrict__ sk_hi, const __nv_bfloat16* __restrict__ sk_lo,
    __nv_bfloat16* __restrict__ out_hi, __nv_bfloat16* __restrict__ out_lo,
    float* __restrict__ out_f32)
{
    extern __shared__ __align__(16) unsigned char dynsmem[];
    uint32_t aAbuf[2];
    {
        uint32_t base = smem_u32(dynsmem);
        aAbuf[0] = base;
        aAbuf[1] = base + 33280;
    }
    float* s_sc = (float*)(dynsmem + 2*33280);
    float* s_sh = s_sc + 64;

    const int tid  = threadIdx.x;
    const int wm   = tid >> 5;
    const int lane = tid & 31;
    const int w0   = blockIdx.x * 128;
    const int h    = blockIdx.y;
    const int b    = blockIdx.z;

    if (BNRELU && tid < 64) {
        float sc = bng[tid] * rsqrtf(bnv[tid] + 1e-5f);
        s_sc[tid] = sc;
        s_sh[tid] = bnb[tid] - bnm[tid] * sc;
    }

    auto stageA = [&](int ky, int sel) {
        const int hs = h + ky - 1;
        const bool hok = (hs >= 0) && (hs < HH);
        const int hc = hok ? hs : 0;
        for (int idx = tid; idx < 260; idx += 128) {
            int r = idx % 130;
            int half = idx / 130;
            int ws = w0 - 1 + r;
            bool ok = hok && (ws >= 0) && (ws < WW);
            int wc = (ws >= 0 && ws < WW) ? ws : 0;
            const char* src = (const char*)((half ? in_lo : in_hi)
                              + ((size_t)((b*HH + hc)*WW + wc))*64);
            uint32_t dstb = aAbuf[sel];
            #pragma unroll
            for (int j = 0; j < 8; j++)
                cpa16z(dstb + swzA(r, half*128 + j*16), src + j*16, ok);
        }
    };

    float d[2][8][4];
    #pragma unroll
    for (int mf = 0; mf < 2; mf++)
        #pragma unroll
        for (int nf = 0; nf < 8; nf++)
            #pragma unroll
            for (int q = 0; q < 4; q++) d[mf][nf][q] = 0.f;

    stageA(0, 0);
    CP_COMMIT();

    for (int ky = 0; ky < 3; ky++) {
        CP_WAIT0();
        __syncthreads();
        if (ky < 2) {                  // prefetch next ky's A into other buffer
            stageA(ky + 1, (ky + 1) & 1);
            CP_COMMIT();
        }
        const uint32_t A_ = aAbuf[ky & 1];

        for (int kx = 0; kx < 3; kx++) {
            const int tap = ky*3 + kx;
            const uint4* fb = Fb + (size_t)tap*1024;   // tap stride = 1024 uint4

            #pragma unroll
            for (int j = 0; j < 4; j++) {
                // B fragments via LDG.128 (same addr all 4 warps -> L1 broadcast)
                uint4 Bh[4], Bl[4];
                #pragma unroll
                for (int g = 0; g < 4; g++) {
                    Bh[g] = __ldg(fb + (size_t)j*256 + g*32 + lane);
                    Bl[g] = __ldg(fb + (size_t)j*256 + 128 + g*32 + lane);
                }
                // A fragments via ldmatrix
                uint32_t Ah[2][4], Al[2][4];
                #pragma unroll
                for (int mf = 0; mf < 2; mf++) {
                    int arow = wm*32 + mf*16 + (lane & 15) + kx;
                    ldsm_x4(Ah[mf], A_ + swzA(arow, j*32 + (lane >> 4)*16));
                    ldsm_x4(Al[mf], A_ + swzA(arow, 128 + j*32 + (lane >> 4)*16));
                }
                #pragma unroll
                for (int mf = 0; mf < 2; mf++)
                    #pragma unroll
                    for (int nf = 0; nf < 8; nf++) {
                        const uint4& f = Bh[nf >> 1];
                        mma_bf16(d[mf][nf], Ah[mf],
                                 (nf & 1) ? f.z : f.x, (nf & 1) ? f.w : f.y);
                    }
                #pragma unroll
                for (int mf = 0; mf < 2; mf++)
                    #pragma unroll
                    for (int nf = 0; nf < 8; nf++) {
                        const uint4& f = Bh[nf >> 1];
                        mma_bf16(d[mf][nf], Al[mf],
                                 (nf & 1) ? f.z : f.x, (nf & 1) ? f.w : f.y);
                    }
                #pragma unroll
                for (int mf = 0; mf < 2; mf++)
                    #pragma unroll
                    for (int nf = 0; nf < 8; nf++) {
                        const uint4& f = Bl[nf >> 1];
                        mma_bf16(d[mf][nf], Ah[mf],
                                 (nf & 1) ? f.z : f.x, (nf & 1) ? f.w : f.y);
                    }
            }
        }
    }

    // ---- epilogue ----
    #pragma unroll
    for (int mf = 0; mf < 2; mf++) {
        #pragma unroll
        for (int rr = 0; rr < 2; rr++) {
            const int p = wm*32 + mf*16 + (lane >> 2) + rr*8;
            const int w = w0 + p;
            const size_t nbase = ((size_t)((b*HH + h)*WW + w))*64;
            #pragma unroll
            for (int nf = 0; nf < 8; nf++) {
                const int cout = nf*8 + (lane & 3)*2;
                float v0 = d[mf][nf][rr*2 + 0];
                float v1 = d[mf][nf][rr*2 + 1];
                if (BNRELU) {
                    v0 = fmaxf(v0 * s_sc[cout]     + s_sh[cout],     0.f);
                    v1 = fmaxf(v1 * s_sc[cout + 1] + s_sh[cout + 1], 0.f);
                }
                if (SKIP) {
                    uint32_t sh2 = *(const uint32_t*)(sk_hi + nbase + cout);
                    uint32_t sl2 = *(const uint32_t*)(sk_lo + nbase + cout);
                    v0 += __bfloat162float(__ushort_as_bfloat16((unsigned short)(sh2 & 0xFFFF)))
                        + __bfloat162float(__ushort_as_bfloat16((unsigned short)(sl2 & 0xFFFF)));
                    v1 += __bfloat162float(__ushort_as_bfloat16((unsigned short)(sh2 >> 16)))
                        + __bfloat162float(__ushort_as_bfloat16((unsigned short)(sl2 >> 16)));
                }
                if (OUTF32) {
                    if (OSTRIDE == 64 || cout < OSTRIDE)
                        out_f32[((size_t)(b*OSTRIDE + cout)*HH + h)*WW + w] = v0;
                    if (OSTRIDE == 64 || cout + 1 < OSTRIDE)
                        out_f32[((size_t)(b*OSTRIDE + cout + 1)*HH + h)*WW + w] = v1;
                } else {
                    __nv_bfloat16 h0 = __float2bfloat16(v0);
                    __nv_bfloat16 h1 = __float2bfloat16(v1);
                    __nv_bfloat16 l0 = __float2bfloat16(v0 - __bfloat162float(h0));
                    __nv_bfloat16 l1 = __float2bfloat16(v1 - __bfloat162float(h1));
                    uint32_t ph = (uint32_t)__bfloat16_as_ushort(h0)
                                | ((uint32_t)__bfloat16_as_ushort(h1) << 16);
                    uint32_t pl = (uint32_t)__bfloat16_as_ushort(l0)
                                | ((uint32_t)__bfloat16_as_ushort(l1) << 16);
                    *(uint32_t*)(out_hi + nbase + cout) = ph;
                    *(uint32_t*)(out_lo + nbase + cout) = pl;
                }
            }
        }
    }
}

// ===========================================================================
// Adaptive filtering
// ===========================================================================
__global__ __launch_bounds__(256) void filt_h_kernel(
    const float* __restrict__ filt, const float* __restrict__ base,
    float* __restrict__ fh)
{
    int idx = blockIdx.x * 256 + threadIdx.x;
    int w  = idx & 511;
    int h  = (idx >> 9) & 511;
    int bc = idx >> 18;
    int ch = bc % 3;
    int b  = bc / 3;

    const float* lp = filt + ((size_t)(b*30 + ch*10)*HH + h)*WW + w;
    float l[5];
    #pragma unroll
    for (int i = 0; i < 5; i++) l[i] = lp[(size_t)i*HWSZ];
    float m = fmaxf(fmaxf(fmaxf(l[0], l[1]), fmaxf(l[2], l[3])), l[4]);
    float e[5], s = 0.f;
    #pragma unroll
    for (int i = 0; i < 5; i++) { e[i] = __expf(l[i] - m); s += e[i]; }
    float inv = 1.f / s;

    const float* bp = base + (size_t)bc*HWSZ + w;
    float r = 0.f;
    #pragma unroll
    for (int i = 0; i < 5; i++) {
        int hh2 = h - 2 + i;
        float bv = (hh2 >= 0 && hh2 < HH) ? bp[(size_t)hh2*WW] : 0.f;
        r += bv * e[i] * inv;
    }
    fh[idx] = r;
}

__global__ __launch_bounds__(256) void filt_w_kernel(
    const float* __restrict__ filt, const float* __restrict__ fh,
    float* __restrict__ out)
{
    int idx = blockIdx.x * 256 + threadIdx.x;
    int w  = idx & 511;
    int h  = (idx >> 9) & 511;
    int bc = idx >> 18;
    int ch = bc % 3;
    int b  = bc / 3;

    const float* lp = filt + ((size_t)(b*30 + ch*10 + 5)*HH + h)*WW + w;
    float l[5];
    #pragma unroll
    for (int i = 0; i < 5; i++) l[i] = lp[(size_t)i*HWSZ];
    float m = fmaxf(fmaxf(fmaxf(l[0], l[1]), fmaxf(l[2], l[3])), l[4]);
    float e[5], s = 0.f;
    #pragma unroll
    for (int i = 0; i < 5; i++) { e[i] = __expf(l[i] - m); s += e[i]; }
    float inv = 1.f / s;

    const float* fp = fh + ((size_t)bc*HH + h)*WW;
    float r = 0.f;
    #pragma unroll
    for (int i = 0; i < 5; i++) {
        int ww2 = w - 2 + i;
        float fv = (ww2 >= 0 && ww2 < WW) ? fp[ww2] : 0.f;
        r += fv * e[i] * inv;
    }
    out[idx] = r;
}

// ===========================================================================
extern "C" void kernel_launch(void* const* d_in, const int* in_sizes, int n_in,
                              void* d_out, int out_size)
{
    const float* fm     = (const float*)d_in[0];
    const float* base   = (const float*)d_in[1];
    const float* wfirst = (const float*)d_in[2];
    const float* kbw1   = (const float*)d_in[3];
    const float* kbg1   = (const float*)d_in[4];
    const float* kbb1   = (const float*)d_in[5];
    const float* kbm1   = (const float*)d_in[6];
    const float* kbv1   = (const float*)d_in[7];
    const float* kbw2   = (const float*)d_in[8];
    const float* kbg2   = (const float*)d_in[9];
    const float* kbb2   = (const float*)d_in[10];
    const float* kbm2   = (const float*)d_in[11];
    const float* kbv2   = (const float*)d_in[12];
    const float* wlast  = (const float*)d_in[13];
    float* out = (float*)d_out;

    float *F, *FHp;
    __nv_bfloat16 *P0h, *P0l, *P1h, *P1l, *P2h, *P2l;
    uint4* Fb;
    cudaGetSymbolAddress((void**)&F,   g_filt);
    cudaGetSymbolAddress((void**)&FHp, g_fh);
    cudaGetSymbolAddress((void**)&P0h, g_P0h);
    cudaGetSymbolAddress((void**)&P0l, g_P0l);
    cudaGetSymbolAddress((void**)&P1h, g_P1h);
    cudaGetSymbolAddress((void**)&P1l, g_P1l);
    cudaGetSymbolAddress((void**)&P2h, g_P2h);
    cudaGetSymbolAddress((void**)&P2l, g_P2l);
    cudaGetSymbolAddress((void**)&Fb,  g_FragB);

    cudaFuncSetAttribute(res_conv_kernel<true,false,false,64>,
                         cudaFuncAttributeMaxDynamicSharedMemorySize, RES_SMEM);
    cudaFuncSetAttribute(res_conv_kernel<true,true,false,64>,
                         cudaFuncAttributeMaxDynamicSharedMemorySize, RES_SMEM);
    cudaFuncSetAttribute(res_conv_kernel<false,false,true,30>,
                         cudaFuncAttributeMaxDynamicSharedMemorySize, RES_SMEM);

    // 1. weight prep -> mma-ready fragments (8 res convs + conv_last padded)
    prep_w_kernel<<<(9*9216 + 255)/256, 256>>>(kbw1, kbw2, wlast, Fb);

    // 2. conv_first -> P0 pair
    dim3 g7(WW/16, HH/8, BATCH);
    conv7x7_kernel<<<g7, 256>>>(fm, wfirst, P0h, P0l);

    // 3. residual blocks
    dim3 gr(WW/128, HH, BATCH);
    const size_t SL = 9216;   // uint4 stride per section
    __nv_bfloat16 *yh = P0h, *yl = P0l;
    __nv_bfloat16 *alt_h = P2h, *alt_l = P2l;
    for (int r = 0; r < 4; r++) {
        res_conv_kernel<true,false,false,64><<<gr, 128, RES_SMEM>>>(
            yh, yl, Fb + (size_t)(r*2+0)*SL,
            kbg1 + r*64, kbb1 + r*64, kbm1 + r*64, kbv1 + r*64,
            nullptr, nullptr, P1h, P1l, nullptr);
        res_conv_kernel<true,true,false,64><<<gr, 128, RES_SMEM>>>(
            P1h, P1l, Fb + (size_t)(r*2+1)*SL,
            kbg2 + r*64, kbb2 + r*64, kbm2 + r*64, kbv2 + r*64,
            yh, yl, alt_h, alt_l, nullptr);
        __nv_bfloat16* th = yh; __nv_bfloat16* tl = yl;
        yh = alt_h; yl = alt_l;
        alt_h = th; alt_l = tl;
    }

    // 4. conv_last via MMA (couts padded 30->64, stride-30 fp32 NCHW epilogue)
    res_conv_kernel<false,false,true,30><<<gr, 128, RES_SMEM>>>(
        yh, yl, Fb + (size_t)8*SL,
        nullptr, nullptr, nullptr, nullptr,
        nullptr, nullptr, nullptr, nullptr, F);

    // 5. adaptive filtering
    int npix = BATCH*3*HWSZ;
    filt_h_kernel<<<npix/256, 256>>>(F, base, FHp);
    filt_w_kernel<<<npix/256, 256>>>(F, FHp, out);
}

// round 15
// speedup vs baseline: 3.6929x; 1.0454x over previous
#include <cuda_runtime.h>
#include <cuda_bf16.h>
#include <cstdint>

#define HH 512
#define WW 512
#define BATCH 2
#define HWSZ (HH*WW)

// ===========================================================================
// Warp-MMA + cp.async helpers (family-compatible)
// ===========================================================================
__device__ __forceinline__ uint32_t smem_u32(const void* p) {
    uint32_t a;
    asm("{ .reg .u64 t; cvta.to.shared.u64 t, %1; cvt.u32.u64 %0, t; }"
        : "=r"(a) : "l"(p));
    return a;
}
__device__ __forceinline__ void ldsm_x4(uint32_t* r, uint32_t addr) {
    asm volatile("ldmatrix.sync.aligned.m8n8.x4.shared.b16 {%0,%1,%2,%3}, [%4];"
        : "=r"(r[0]), "=r"(r[1]), "=r"(r[2]), "=r"(r[3]) : "r"(addr));
}
__device__ __forceinline__ void mma_bf16(float* d, const uint32_t* a,
                                         uint32_t b0, uint32_t b1) {
    asm volatile("mma.sync.aligned.m16n8k16.row.col.f32.bf16.bf16.f32 "
        "{%0,%1,%2,%3}, {%4,%5,%6,%7}, {%8,%9}, {%0,%1,%2,%3};"
        : "+f"(d[0]), "+f"(d[1]), "+f"(d[2]), "+f"(d[3])
        : "r"(a[0]), "r"(a[1]), "r"(a[2]), "r"(a[3]), "r"(b0), "r"(b1));
}
__device__ __forceinline__ void cpa16z(uint32_t dst, const void* src, int ok) {
    asm volatile("cp.async.cg.shared.global [%0], [%1], 16, %2;"
                 :: "r"(dst), "l"(src), "r"(ok ? 16 : 0) : "memory");
}
#define CP_COMMIT() asm volatile("cp.async.commit_group;" ::: "memory")
#define CP_WAIT0()  asm volatile("cp.async.wait_group 0;" ::: "memory")

// swizzle for 256B-row tiles (A smem): chunk' = (c&8) | ((c^row)&7)
__device__ __forceinline__ uint32_t swzA(int row, int kbyte) {
    int c = kbyte >> 4;
    int cs = (c & 8) | ((c ^ row) & 7);
    return (uint32_t)(row * 256 + (cs << 4));
}

// ===========================================================================
// Persistent scratch
// ===========================================================================
__device__ float g_filt[(size_t)BATCH*30*HWSZ];
__device__ float g_fh[(size_t)BATCH*3*HWSZ];
// NHWC bf16 activation pairs [b][h][w][c]
__device__ __nv_bfloat16 g_P0h[(size_t)BATCH*HWSZ*64];
__device__ __nv_bfloat16 g_P0l[(size_t)BATCH*HWSZ*64];
__device__ __nv_bfloat16 g_P1h[(size_t)BATCH*HWSZ*64];
__device__ __nv_bfloat16 g_P1l[(size_t)BATCH*HWSZ*64];
__device__ __nv_bfloat16 g_P2h[(size_t)BATCH*HWSZ*64];
__device__ __nv_bfloat16 g_P2l[(size_t)BATCH*HWSZ*64];
// Pre-shuffled B fragments: [sec=9][tap=9][j=4][term=2][g=4][lane=32] uint4.
// strides (uint4): lane=1, g=32, term=128, j=256, tap=1024, sec=9216
__device__ uint4 g_FragB[(size_t)9*9*4*2*4*32];

// ===========================================================================
// Weight prep: build mma-ready B fragments (hi/lo split) from raw fp32 weights
// ===========================================================================
__global__ void prep_w_kernel(const float* __restrict__ w1, const float* __restrict__ w2,
                              const float* __restrict__ wlast,
                              uint4* __restrict__ Fb)
{
    int idx = blockIdx.x * 256 + threadIdx.x;
    if (idx >= 9*9216) return;
    int lane = idx & 31;
    int g    = (idx >> 5) & 3;
    int term = (idx >> 7) & 1;
    int j    = (idx >> 8) & 3;
    int tap  = (idx >> 10) % 9;
    int sec  = idx / 9216;
    int ky = tap / 3, kx = tap % 3;
    int nl = lane >> 2, kk = (lane & 3) * 2;
    int n0 = g*16 + nl, n1 = n0 + 8;
    int k0 = j*16 + kk;

    auto enc = [&](int co, int ci) -> uint32_t {
        float v;
        if (sec < 8) {
            int conv = sec & 1, r = sec >> 1;
            const float* s = conv ? w2 : w1;
            v = s[(((r*64 + co)*64 + ci)*3 + ky)*3 + kx];
        } else {
            v = (co < 30) ? wlast[((co*64 + ci)*3 + ky)*3 + kx] : 0.f;
        }
        __nv_bfloat16 h = __float2bfloat16(v);
        if (term) h = __float2bfloat16(v - __bfloat162float(h));
        return (uint32_t)__bfloat16_as_ushort(h);
    };
    uint4 o;
    o.x = enc(n0, k0)     | (enc(n0, k0 + 1) << 16);
    o.y = enc(n0, k0 + 8) | (enc(n0, k0 + 9) << 16);
    o.z = enc(n1, k0)     | (enc(n1, k0 + 1) << 16);
    o.w = enc(n1, k0 + 8) | (enc(n1, k0 + 9) << 16);
    Fb[idx] = o;
}

// ===========================================================================
// conv 7x7, Cin=6 -> 64, pad 3, ReLU. Scalar fp32; outputs NHWC bf16 hi/lo.
// ===========================================================================
__global__ __launch_bounds__(256) void conv7x7_kernel(
    const float* __restrict__ in, const float* __restrict__ wt,
    __nv_bfloat16* __restrict__ out_hi, __nv_bfloat16* __restrict__ out_lo)
{
    __shared__ float s_in[6][14][24];
    __shared__ float s_w[64][7][8];

    const int tid  = threadIdx.x;
    const int cg   = tid >> 5;
    const int slot = tid & 31;
    const int pr   = slot >> 2;
    const int pc4  = (slot & 3) * 4;
    const int h0   = blockIdx.y * 8;
    const int w0   = blockIdx.x * 16;
    const int b    = blockIdx.z;

    for (int i = tid; i < 6*14*22; i += 256) {
        int ci = i / (14*22);
        int r  = (i / 22) % 14;
        int c  = i % 22;
        int gh = h0 - 3 + r;
        int gw = w0 - 3 + c;
        float v = 0.f;
        if (gh >= 0 && gh < HH && gw >= 0 && gw < WW)
            v = in[((b*6 + ci)*HH + gh)*WW + gw];
        s_in[ci][r][c] = v;
    }

    float acc[8][4];
    #pragma unroll
    for (int c = 0; c < 8; c++)
        #pragma unroll
        for (int p = 0; p < 4; p++) acc[c][p] = 0.f;

    for (int cin = 0; cin < 6; cin++) {
        __syncthreads();
        for (int i = tid; i < 64*49; i += 256) {
            int co = i / 49, k = i % 49;
            s_w[co][k/7][k%7] = wt[(co*6 + cin)*49 + k];
        }
        __syncthreads();
        #pragma unroll 1
        for (int ky = 0; ky < 7; ky++) {
            float xr[10];
            const float* rp = &s_in[cin][pr + ky][pc4];
            #pragma unroll
            for (int j = 0; j < 10; j++) xr[j] = rp[j];
            #pragma unroll
            for (int c = 0; c < 8; c++) {
                const float* wp = &s_w[cg*8 + c][ky][0];
                float wv[7];
                #pragma unroll
                for (int q = 0; q < 7; q++) wv[q] = wp[q];
                #pragma unroll
                for (int p = 0; p < 4; p++) {
                    float s = acc[c][p];
                    #pragma unroll
                    for (int q = 0; q < 7; q++) s += xr[p+q] * wv[q];
                    acc[c][p] = s;
                }
            }
        }
    }

    const int h = h0 + pr;
    #pragma unroll
    for (int p = 0; p < 4; p++) {
        int w = w0 + pc4 + p;
        size_t nb = ((size_t)((b*HH + h)*WW + w))*64 + cg*8;
        union { uint4 u; __nv_bfloat16 x[8]; } Uh, Ul;
        #pragma unroll
        for (int c = 0; c < 8; c++) {
            float v = fmaxf(acc[c][p], 0.f);
            __nv_bfloat16 hh = __float2bfloat16(v);
            Uh.x[c] = hh;
            Ul.x[c] = __float2bfloat16(v - __bfloat162float(hh));
        }
        *(uint4*)(out_hi + nb) = Uh.u;
        *(uint4*)(out_lo + nb) = Ul.u;
    }
}

// ===========================================================================
// conv3x3 64->64 (or 64->30 padded) via mma.sync bf16, 3-term split.
// CTA: 128 thr = 4 warps, each M=32 x N=64 (tile M=128, N=64).
// A double-buffered per ky via cp.async; B fragments register-double-buffered:
// step q's MMAs overlap step q+1's B LDGs. Fully unrolled (ky,kx,j).
// ===========================================================================
#define RES_SMEM (2*33280 + 512)

template<bool BNRELU, bool SKIP, bool OUTF32, int OSTRIDE>
__global__ __launch_bounds__(128, 3) void res_conv_kernel(
    const __nv_bfloat16* __restrict__ in_hi, const __nv_bfloat16* __restrict__ in_lo,
    const uint4* __restrict__ Fb,
    const float* __restrict__ bng, const float* __restrict__ bnb,
    const float* __restrict__ bnm, const float* __restrict__ bnv,
    const __nv_bfloat16* __restrict__ sk_hi, const __nv_bfloat16* __restrict__ sk_lo,
    __nv_bfloat16* __restrict__ out_hi, __nv_bfloat16* __restrict__ out_lo,
    float* __restrict__ out_f32)
{
    extern __shared__ __align__(16) unsigned char dynsmem[];
    uint32_t aAbuf[2];
    {
        uint32_t base = smem_u32(dynsmem);
        aAbuf[0] = base;
        aAbuf[1] = base + 33280;
    }
    float* s_sc = (float*)(dynsmem + 2*33280);
    float* s_sh = s_sc + 64;

    const int tid  = threadIdx.x;
    const int wm   = tid >> 5;
    const int lane = tid & 31;
    const int w0   = blockIdx.x * 128;
    const int h    = blockIdx.y;
    const int b    = blockIdx.z;

    if (BNRELU && tid < 64) {
        float sc = bng[tid] * rsqrtf(bnv[tid] + 1e-5f);
        s_sc[tid] = sc;
        s_sh[tid] = bnb[tid] - bnm[tid] * sc;
    }

    auto stageA = [&](int ky, int sel) {
        const int hs = h + ky - 1;
        const bool hok = (hs >= 0) && (hs < HH);
        const int hc = hok ? hs : 0;
        for (int idx = tid; idx < 260; idx += 128) {
            int r = idx % 130;
            int half = idx / 130;
            int ws = w0 - 1 + r;
            bool ok = hok && (ws >= 0) && (ws < WW);
            int wc = (ws >= 0 && ws < WW) ? ws : 0;
            const char* src = (const char*)((half ? in_lo : in_hi)
                              + ((size_t)((b*HH + hc)*WW + wc))*64);
            uint32_t dstb = aAbuf[sel];
            #pragma unroll
            for (int j = 0; j < 8; j++)
                cpa16z(dstb + swzA(r, half*128 + j*16), src + j*16, ok);
        }
    };

    // B fragment load: linear step q = tap*4 + j -> Bbuf slot.
    // Layout strides (uint4): j=256, tap=1024. dst[0..3]=hi, dst[4..7]=lo.
    auto loadB = [&](int q, uint4* dst) {
        const uint4* fp = Fb + (size_t)(q >> 2)*1024 + (size_t)(q & 3)*256 + lane;
        #pragma unroll
        for (int g = 0; g < 4; g++) {
            dst[g]     = __ldg(fp + g*32);
            dst[4 + g] = __ldg(fp + 128 + g*32);
        }
    };

    float d[2][8][4];
    #pragma unroll
    for (int mf = 0; mf < 2; mf++)
        #pragma unroll
        for (int nf = 0; nf < 8; nf++)
            #pragma unroll
            for (int q = 0; q < 4; q++) d[mf][nf][q] = 0.f;

    stageA(0, 0);
    CP_COMMIT();

    uint4 Bbuf[2][8];
    loadB(0, Bbuf[0]);

    #pragma unroll
    for (int ky = 0; ky < 3; ky++) {
        CP_WAIT0();
        __syncthreads();
        if (ky < 2) {                  // prefetch next ky's A into other buffer
            stageA(ky + 1, (ky + 1) & 1);
            CP_COMMIT();
        }
        const uint32_t A_ = aAbuf[ky & 1];

        #pragma unroll
        for (int kx = 0; kx < 3; kx++) {
            #pragma unroll
            for (int j = 0; j < 4; j++) {
                const int q = (ky*3 + kx)*4 + j;
                const int cur = q & 1;
                // prefetch next step's B fragments into the other buffer
                loadB(q < 35 ? q + 1 : 35, Bbuf[cur ^ 1]);
                // A fragments via ldmatrix
                uint32_t Ah[2][4], Al[2][4];
                #pragma unroll
                for (int mf = 0; mf < 2; mf++) {
                    int arow = wm*32 + mf*16 + (lane & 15) + kx;
                    ldsm_x4(Ah[mf], A_ + swzA(arow, j*32 + (lane >> 4)*16));
                    ldsm_x4(Al[mf], A_ + swzA(arow, 128 + j*32 + (lane >> 4)*16));
                }
                const uint4* Bc = Bbuf[cur];
                #pragma unroll
                for (int mf = 0; mf < 2; mf++)
                    #pragma unroll
                    for (int nf = 0; nf < 8; nf++) {
                        const uint4& f = Bc[nf >> 1];
                        mma_bf16(d[mf][nf], Ah[mf],
                                 (nf & 1) ? f.z : f.x, (nf & 1) ? f.w : f.y);
                    }
                #pragma unroll
                for (int mf = 0; mf < 2; mf++)
                    #pragma unroll
                    for (int nf = 0; nf < 8; nf++) {
                        const uint4& f = Bc[nf >> 1];
                        mma_bf16(d[mf][nf], Al[mf],
                                 (nf & 1) ? f.z : f.x, (nf & 1) ? f.w : f.y);
                    }
                #pragma unroll
                for (int mf = 0; mf < 2; mf++)
                    #pragma unroll
                    for (int nf = 0; nf < 8; nf++) {
                        const uint4& f = Bc[4 + (nf >> 1)];
                        mma_bf16(d[mf][nf], Ah[mf],
                                 (nf & 1) ? f.z : f.x, (nf & 1) ? f.w : f.y);
                    }
            }
        }
    }

    // ---- epilogue ----
    #pragma unroll
    for (int mf = 0; mf < 2; mf++) {
        #pragma unroll
        for (int rr = 0; rr < 2; rr++) {
            const int p = wm*32 + mf*16 + (lane >> 2) + rr*8;
            const int w = w0 + p;
            const size_t nbase = ((size_t)((b*HH + h)*WW + w))*64;
            #pragma unroll
            for (int nf = 0; nf < 8; nf++) {
                const int cout = nf*8 + (lane & 3)*2;
                float v0 = d[mf][nf][rr*2 + 0];
                float v1 = d[mf][nf][rr*2 + 1];
                if (BNRELU) {
                    v0 = fmaxf(v0 * s_sc[cout]     + s_sh[cout],     0.f);
                    v1 = fmaxf(v1 * s_sc[cout + 1] + s_sh[cout + 1], 0.f);
                }
                if (SKIP) {
                    uint32_t sh2 = *(const uint32_t*)(sk_hi + nbase + cout);
                    uint32_t sl2 = *(const uint32_t*)(sk_lo + nbase + cout);
                    v0 += __bfloat162float(__ushort_as_bfloat16((unsigned short)(sh2 & 0xFFFF)))
                        + __bfloat162float(__ushort_as_bfloat16((unsigned short)(sl2 & 0xFFFF)));
                    v1 += __bfloat162float(__ushort_as_bfloat16((unsigned short)(sh2 >> 16)))
                        + __bfloat162float(__ushort_as_bfloat16((unsigned short)(sl2 >> 16)));
                }
                if (OUTF32) {
                    if (OSTRIDE == 64 || cout < OSTRIDE)
                        out_f32[((size_t)(b*OSTRIDE + cout)*HH + h)*WW + w] = v0;
                    if (OSTRIDE == 64 || cout + 1 < OSTRIDE)
                        out_f32[((size_t)(b*OSTRIDE + cout + 1)*HH + h)*WW + w] = v1;
                } else {
                    __nv_bfloat16 h0 = __float2bfloat16(v0);
                    __nv_bfloat16 h1 = __float2bfloat16(v1);
                    __nv_bfloat16 l0 = __float2bfloat16(v0 - __bfloat162float(h0));
                    __nv_bfloat16 l1 = __float2bfloat16(v1 - __bfloat162float(h1));
                    uint32_t ph = (uint32_t)__bfloat16_as_ushort(h0)
                                | ((uint32_t)__bfloat16_as_ushort(h1) << 16);
                    uint32_t pl = (uint32_t)__bfloat16_as_ushort(l0)
                                | ((uint32_t)__bfloat16_as_ushort(l1) << 16);
                    *(uint32_t*)(out_hi + nbase + cout) = ph;
                    *(uint32_t*)(out_lo + nbase + cout) = pl;
                }
            }
        }
    }
}

// ===========================================================================
// Adaptive filtering
// ===========================================================================
__global__ __launch_bounds__(256) void filt_h_kernel(
    const float* __restrict__ filt, const float* __restrict__ base,
    float* __restrict__ fh)
{
    int idx = blockIdx.x * 256 + threadIdx.x;
    int w  = idx & 511;
    int h  = (idx >> 9) & 511;
    int bc = idx >> 18;
    int ch = bc % 3;
    int b  = bc / 3;

    const float* lp = filt + ((size_t)(b*30 + ch*10)*HH + h)*WW + w;
    float l[5];
    #pragma unroll
    for (int i = 0; i < 5; i++) l[i] = lp[(size_t)i*HWSZ];
    float m = fmaxf(fmaxf(fmaxf(l[0], l[1]), fmaxf(l[2], l[3])), l[4]);
    float e[5], s = 0.f;
    #pragma unroll
    for (int i = 0; i < 5; i++) { e[i] = __expf(l[i] - m); s += e[i]; }
    float inv = 1.f / s;

    const float* bp = base + (size_t)bc*HWSZ + w;
    float r = 0.f;
    #pragma unroll
    for (int i = 0; i < 5; i++) {
        int hh2 = h - 2 + i;
        float bv = (hh2 >= 0 && hh2 < HH) ? bp[(size_t)hh2*WW] : 0.f;
        r += bv * e[i] * inv;
    }
    fh[idx] = r;
}

__global__ __launch_bounds__(256) void filt_w_kernel(
    const float* __restrict__ filt, const float* __restrict__ fh,
    float* __restrict__ out)
{
    int idx = blockIdx.x * 256 + threadIdx.x;
    int w  = idx & 511;
    int h  = (idx >> 9) & 511;
    int bc = idx >> 18;
    int ch = bc % 3;
    int b  = bc / 3;

    const float* lp = filt + ((size_t)(b*30 + ch*10 + 5)*HH + h)*WW + w;
    float l[5];
    #pragma unroll
    for (int i = 0; i < 5; i++) l[i] = lp[(size_t)i*HWSZ];
    float m = fmaxf(fmaxf(fmaxf(l[0], l[1]), fmaxf(l[2], l[3])), l[4]);
    float e[5], s = 0.f;
    #pragma unroll
    for (int i = 0; i < 5; i++) { e[i] = __expf(l[i] - m); s += e[i]; }
    float inv = 1.f / s;

    const float* fp = fh + ((size_t)bc*HH + h)*WW;
    float r = 0.f;
    #pragma unroll
    for (int i = 0; i < 5; i++) {
        int ww2 = w - 2 + i;
        float fv = (ww2 >= 0 && ww2 < WW) ? fp[ww2] : 0.f;
        r += fv * e[i] * inv;
    }
    out[idx] = r;
}

// ===========================================================================
extern "C" void kernel_launch(void* const* d_in, const int* in_sizes, int n_in,
                              void* d_out, int out_size)
{
    const float* fm     = (const float*)d_in[0];
    const float* base   = (const float*)d_in[1];
    const float* wfirst = (const float*)d_in[2];
    const float* kbw1   = (const float*)d_in[3];
    const float* kbg1   = (const float*)d_in[4];
    const float* kbb1   = (const float*)d_in[5];
    const float* kbm1   = (const float*)d_in[6];
    const float* kbv1   = (const float*)d_in[7];
    const float* kbw2   = (const float*)d_in[8];
    const float* kbg2   = (const float*)d_in[9];
    const float* kbb2   = (const float*)d_in[10];
    const float* kbm2   = (const float*)d_in[11];
    const float* kbv2   = (const float*)d_in[12];
    const float* wlast  = (const float*)d_in[13];
    float* out = (float*)d_out;

    float *F, *FHp;
    __nv_bfloat16 *P0h, *P0l, *P1h, *P1l, *P2h, *P2l;
    uint4* Fb;
    cudaGetSymbolAddress((void**)&F,   g_filt);
    cudaGetSymbolAddress((void**)&FHp, g_fh);
    cudaGetSymbolAddress((void**)&P0h, g_P0h);
    cudaGetSymbolAddress((void**)&P0l, g_P0l);
    cudaGetSymbolAddress((void**)&P1h, g_P1h);
    cudaGetSymbolAddress((void**)&P1l, g_P1l);
    cudaGetSymbolAddress((void**)&P2h, g_P2h);
    cudaGetSymbolAddress((void**)&P2l, g_P2l);
    cudaGetSymbolAddress((void**)&Fb,  g_FragB);

    cudaFuncSetAttribute(res_conv_kernel<true,false,false,64>,
                         cudaFuncAttributeMaxDynamicSharedMemorySize, RES_SMEM);
    cudaFuncSetAttribute(res_conv_kernel<true,true,false,64>,
                         cudaFuncAttributeMaxDynamicSharedMemorySize, RES_SMEM);
    cudaFuncSetAttribute(res_conv_kernel<false,false,true,30>,
                         cudaFuncAttributeMaxDynamicSharedMemorySize, RES_SMEM);

    // 1. weight prep -> mma-ready fragments (8 res convs + conv_last padded)
    prep_w_kernel<<<(9*9216 + 255)/256, 256>>>(kbw1, kbw2, wlast, Fb);

    // 2. conv_first -> P0 pair
    dim3 g7(WW/16, HH/8, BATCH);
    conv7x7_kernel<<<g7, 256>>>(fm, wfirst, P0h, P0l);

    // 3. residual blocks
    dim3 gr(WW/128, HH, BATCH);
    const size_t SL = 9216;   // uint4 stride per section
    __nv_bfloat16 *yh = P0h, *yl = P0l;
    __nv_bfloat16 *alt_h = P2h, *alt_l = P2l;
    for (int r = 0; r < 4; r++) {
        res_conv_kernel<true,false,false,64><<<gr, 128, RES_SMEM>>>(
            yh, yl, Fb + (size_t)(r*2+0)*SL,
            kbg1 + r*64, kbb1 + r*64, kbm1 + r*64, kbv1 + r*64,
            nullptr, nullptr, P1h, P1l, nullptr);
        res_conv_kernel<true,true,false,64><<<gr, 128, RES_SMEM>>>(
            P1h, P1l, Fb + (size_t)(r*2+1)*SL,
            kbg2 + r*64, kbb2 + r*64, kbm2 + r*64, kbv2 + r*64,
            yh, yl, alt_h, alt_l, nullptr);
        __nv_bfloat16* th = yh; __nv_bfloat16* tl = yl;
        yh = alt_h; yl = alt_l;
        alt_h = th; alt_l = tl;
    }

    // 4. conv_last via MMA (couts padded 30->64, stride-30 fp32 NCHW epilogue)
    res_conv_kernel<false,false,true,30><<<gr, 128, RES_SMEM>>>(
        yh, yl, Fb + (size_t)8*SL,
        nullptr, nullptr, nullptr, nullptr,
        nullptr, nullptr, nullptr, nullptr, F);

    // 5. adaptive filtering
    int npix = BATCH*3*HWSZ;
    filt_h_kernel<<<npix/256, 256>>>(F, base, FHp);
    filt_w_kernel<<<npix/256, 256>>>(F, FHp, out);
}

// round 16
// speedup vs baseline: 3.7086x; 1.0043x over previous
#include <cuda_runtime.h>
#include <cuda_bf16.h>
#include <cstdint>

#define HH 512
#define WW 512
#define BATCH 2
#define HWSZ (HH*WW)

// ===========================================================================
// Warp-MMA + cp.async helpers (family-compatible)
// ===========================================================================
__device__ __forceinline__ uint32_t smem_u32(const void* p) {
    uint32_t a;
    asm("{ .reg .u64 t; cvta.to.shared.u64 t, %1; cvt.u32.u64 %0, t; }"
        : "=r"(a) : "l"(p));
    return a;
}
__device__ __forceinline__ void ldsm_x4(uint32_t* r, uint32_t addr) {
    asm volatile("ldmatrix.sync.aligned.m8n8.x4.shared.b16 {%0,%1,%2,%3}, [%4];"
        : "=r"(r[0]), "=r"(r[1]), "=r"(r[2]), "=r"(r[3]) : "r"(addr));
}
__device__ __forceinline__ void mma_bf16(float* d, const uint32_t* a,
                                         uint32_t b0, uint32_t b1) {
    asm volatile("mma.sync.aligned.m16n8k16.row.col.f32.bf16.bf16.f32 "
        "{%0,%1,%2,%3}, {%4,%5,%6,%7}, {%8,%9}, {%0,%1,%2,%3};"
        : "+f"(d[0]), "+f"(d[1]), "+f"(d[2]), "+f"(d[3])
        : "r"(a[0]), "r"(a[1]), "r"(a[2]), "r"(a[3]), "r"(b0), "r"(b1));
}
__device__ __forceinline__ void cpa16z(uint32_t dst, const void* src, int ok) {
    asm volatile("cp.async.cg.shared.global [%0], [%1], 16, %2;"
                 :: "r"(dst), "l"(src), "r"(ok ? 16 : 0) : "memory");
}
#define CP_COMMIT() asm volatile("cp.async.commit_group;" ::: "memory")
#define CP_WAIT0()  asm volatile("cp.async.wait_group 0;" ::: "memory")

// swizzle for 256B-row tiles (A smem): chunk' = (c&8) | ((c^row)&7)
__device__ __forceinline__ uint32_t swzA(int row, int kbyte) {
    int c = kbyte >> 4;
    int cs = (c & 8) | ((c ^ row) & 7);
    return (uint32_t)(row * 256 + (cs << 4));
}

// ===========================================================================
// Persistent scratch
// ===========================================================================
__device__ float g_filt[(size_t)BATCH*30*HWSZ];
__device__ float g_fh[(size_t)BATCH*3*HWSZ];
// NHWC bf16 activation pairs [b][h][w][c]
__device__ __nv_bfloat16 g_P0h[(size_t)BATCH*HWSZ*64];
__device__ __nv_bfloat16 g_P0l[(size_t)BATCH*HWSZ*64];
__device__ __nv_bfloat16 g_P1h[(size_t)BATCH*HWSZ*64];
__device__ __nv_bfloat16 g_P1l[(size_t)BATCH*HWSZ*64];
__device__ __nv_bfloat16 g_P2h[(size_t)BATCH*HWSZ*64];
__device__ __nv_bfloat16 g_P2l[(size_t)BATCH*HWSZ*64];
// Pre-shuffled B fragments: [sec=9][tap=9][j=4][term=2][g=4][lane=32] uint4.
// strides (uint4): lane=1, g=32, term=128, j=256, tap=1024, sec=9216
__device__ uint4 g_FragB[(size_t)9*9*4*2*4*32];

// ===========================================================================
// Weight prep: build mma-ready B fragments (hi/lo split) from raw fp32 weights
// ===========================================================================
__global__ void prep_w_kernel(const float* __restrict__ w1, const float* __restrict__ w2,
                              const float* __restrict__ wlast,
                              uint4* __restrict__ Fb)
{
    int idx = blockIdx.x * 256 + threadIdx.x;
    if (idx >= 9*9216) return;
    int lane = idx & 31;
    int g    = (idx >> 5) & 3;
    int term = (idx >> 7) & 1;
    int j    = (idx >> 8) & 3;
    int tap  = (idx >> 10) % 9;
    int sec  = idx / 9216;
    int ky = tap / 3, kx = tap % 3;
    int nl = lane >> 2, kk = (lane & 3) * 2;
    int n0 = g*16 + nl, n1 = n0 + 8;
    int k0 = j*16 + kk;

    auto enc = [&](int co, int ci) -> uint32_t {
        float v;
        if (sec < 8) {
            int conv = sec & 1, r = sec >> 1;
            const float* s = conv ? w2 : w1;
            v = s[(((r*64 + co)*64 + ci)*3 + ky)*3 + kx];
        } else {
            v = (co < 30) ? wlast[((co*64 + ci)*3 + ky)*3 + kx] : 0.f;
        }
        __nv_bfloat16 h = __float2bfloat16(v);
        if (term) h = __float2bfloat16(v - __bfloat162float(h));
        return (uint32_t)__bfloat16_as_ushort(h);
    };
    uint4 o;
    o.x = enc(n0, k0)     | (enc(n0, k0 + 1) << 16);
    o.y = enc(n0, k0 + 8) | (enc(n0, k0 + 9) << 16);
    o.z = enc(n1, k0)     | (enc(n1, k0 + 1) << 16);
    o.w = enc(n1, k0 + 8) | (enc(n1, k0 + 9) << 16);
    Fb[idx] = o;
}

// ===========================================================================
// conv 7x7, Cin=6 -> 64, pad 3, ReLU. Scalar fp32; outputs NHWC bf16 hi/lo.
// ===========================================================================
__global__ __launch_bounds__(256) void conv7x7_kernel(
    const float* __restrict__ in, const float* __restrict__ wt,
    __nv_bfloat16* __restrict__ out_hi, __nv_bfloat16* __restrict__ out_lo)
{
    __shared__ float s_in[6][14][24];
    __shared__ float s_w[64][7][8];

    const int tid  = threadIdx.x;
    const int cg   = tid >> 5;
    const int slot = tid & 31;
    const int pr   = slot >> 2;
    const int pc4  = (slot & 3) * 4;
    const int h0   = blockIdx.y * 8;
    const int w0   = blockIdx.x * 16;
    const int b    = blockIdx.z;

    for (int i = tid; i < 6*14*22; i += 256) {
        int ci = i / (14*22);
        int r  = (i / 22) % 14;
        int c  = i % 22;
        int gh = h0 - 3 + r;
        int gw = w0 - 3 + c;
        float v = 0.f;
        if (gh >= 0 && gh < HH && gw >= 0 && gw < WW)
            v = in[((b*6 + ci)*HH + gh)*WW + gw];
        s_in[ci][r][c] = v;
    }

    float acc[8][4];
    #pragma unroll
    for (int c = 0; c < 8; c++)
        #pragma unroll
        for (int p = 0; p < 4; p++) acc[c][p] = 0.f;

    for (int cin = 0; cin < 6; cin++) {
        __syncthreads();
        for (int i = tid; i < 64*49; i += 256) {
            int co = i / 49, k = i % 49;
            s_w[co][k/7][k%7] = wt[(co*6 + cin)*49 + k];
        }
        __syncthreads();
        #pragma unroll 1
        for (int ky = 0; ky < 7; ky++) {
            float xr[10];
            const float* rp = &s_in[cin][pr + ky][pc4];
            #pragma unroll
            for (int j = 0; j < 10; j++) xr[j] = rp[j];
            #pragma unroll
            for (int c = 0; c < 8; c++) {
                const float* wp = &s_w[cg*8 + c][ky][0];
                float wv[7];
                #pragma unroll
                for (int q = 0; q < 7; q++) wv[q] = wp[q];
                #pragma unroll
                for (int p = 0; p < 4; p++) {
                    float s = acc[c][p];
                    #pragma unroll
                    for (int q = 0; q < 7; q++) s += xr[p+q] * wv[q];
                    acc[c][p] = s;
                }
            }
        }
    }

    const int h = h0 + pr;
    #pragma unroll
    for (int p = 0; p < 4; p++) {
        int w = w0 + pc4 + p;
        size_t nb = ((size_t)((b*HH + h)*WW + w))*64 + cg*8;
        union { uint4 u; __nv_bfloat16 x[8]; } Uh, Ul;
        #pragma unroll
        for (int c = 0; c < 8; c++) {
            float v = fmaxf(acc[c][p], 0.f);
            __nv_bfloat16 hh = __float2bfloat16(v);
            Uh.x[c] = hh;
            Ul.x[c] = __float2bfloat16(v - __bfloat162float(hh));
        }
        *(uint4*)(out_hi + nb) = Uh.u;
        *(uint4*)(out_lo + nb) = Ul.u;
    }
}

// ===========================================================================
// conv3x3 64->64 (or 64->30 padded) via mma.sync bf16, 3-term split.
// CTA: 128 thr = 4 warps, each M=32 x N=64 (tile M=128, N=64).
// A double-buffered per ky via cp.async. Register pipelines:
//   - B-hi fragments double-buffered across steps (prefetch q+1)
//   - B-lo fragments loaded JIT at step start (covered by passes 1-2)
//   - A fragments double-buffered across j (prefetch j+1's ldsm)
// ===========================================================================
#define RES_SMEM (2*33280 + 512)

template<bool BNRELU, bool SKIP, bool OUTF32, int OSTRIDE>
__global__ __launch_bounds__(128, 3) void res_conv_kernel(
    const __nv_bfloat16* __restrict__ in_hi, const __nv_bfloat16* __restrict__ in_lo,
    const uint4* __restrict__ Fb,
    const float* __restrict__ bng, const float* __restrict__ bnb,
    const float* __restrict__ bnm, const float* __restrict__ bnv,
    const __nv_bfloat16* __restrict__ sk_hi, const __nv_bfloat16* __restrict__ sk_lo,
    __nv_bfloat16* __restrict__ out_hi, __nv_bfloat16* __restrict__ out_lo,
    float* __restrict__ out_f32)
{
    extern __shared__ __align__(16) unsigned char dynsmem[];
    uint32_t aAbuf[2];
    {
        uint32_t base = smem_u32(dynsmem);
        aAbuf[0] = base;
        aAbuf[1] = base + 33280;
    }
    float* s_sc = (float*)(dynsmem + 2*33280);
    float* s_sh = s_sc + 64;

    const int tid  = threadIdx.x;
    const int wm   = tid >> 5;
    const int lane = tid & 31;
    const int w0   = blockIdx.x * 128;
    const int h    = blockIdx.y;
    const int b    = blockIdx.z;

    if (BNRELU && tid < 64) {
        float sc = bng[tid] * rsqrtf(bnv[tid] + 1e-5f);
        s_sc[tid] = sc;
        s_sh[tid] = bnb[tid] - bnm[tid] * sc;
    }

    auto stageA = [&](int ky, int sel) {
        const int hs = h + ky - 1;
        const bool hok = (hs >= 0) && (hs < HH);
        const int hc = hok ? hs : 0;
        for (int idx = tid; idx < 260; idx += 128) {
            int r = idx % 130;
            int half = idx / 130;
            int ws = w0 - 1 + r;
            bool ok = hok && (ws >= 0) && (ws < WW);
            int wc = (ws >= 0 && ws < WW) ? ws : 0;
            const char* src = (const char*)((half ? in_lo : in_hi)
                              + ((size_t)((b*HH + hc)*WW + wc))*64);
            uint32_t dstb = aAbuf[sel];
            #pragma unroll
            for (int j = 0; j < 8; j++)
                cpa16z(dstb + swzA(r, half*128 + j*16), src + j*16, ok);
        }
    };

    // B fragment loads: step q = tap*4 + j. strides (uint4): j=256, tap=1024.
    auto loadBhi = [&](int q, uint4* dst) {
        const uint4* fp = Fb + (size_t)(q >> 2)*1024 + (size_t)(q & 3)*256 + lane;
        #pragma unroll
        for (int g = 0; g < 4; g++) dst[g] = __ldg(fp + g*32);
    };
    auto loadBlo = [&](int q, uint4* dst) {
        const uint4* fp = Fb + (size_t)(q >> 2)*1024 + (size_t)(q & 3)*256 + 128 + lane;
        #pragma unroll
        for (int g = 0; g < 4; g++) dst[g] = __ldg(fp + g*32);
    };
    // A fragments for (kx, j): dst[term][mf][4]
    auto loadAfrag = [&](uint32_t A_, int kx, int j, uint32_t (*dst)[2][4]) {
        #pragma unroll
        for (int mf = 0; mf < 2; mf++) {
            int arow = wm*32 + mf*16 + (lane & 15) + kx;
            ldsm_x4(dst[0][mf], A_ + swzA(arow, j*32 + (lane >> 4)*16));
            ldsm_x4(dst[1][mf], A_ + swzA(arow, 128 + j*32 + (lane >> 4)*16));
        }
    };

    float d[2][8][4];
    #pragma unroll
    for (int mf = 0; mf < 2; mf++)
        #pragma unroll
        for (int nf = 0; nf < 8; nf++)
            #pragma unroll
            for (int q = 0; q < 4; q++) d[mf][nf][q] = 0.f;

    stageA(0, 0);
    CP_COMMIT();

    uint4 Bhi[2][4];
    loadBhi(0, Bhi[0]);

    #pragma unroll
    for (int ky = 0; ky < 3; ky++) {
        CP_WAIT0();
        __syncthreads();
        if (ky < 2) {                  // prefetch next ky's A into other buffer
            stageA(ky + 1, (ky + 1) & 1);
            CP_COMMIT();
        }
        const uint32_t A_ = aAbuf[ky & 1];

        #pragma unroll
        for (int kx = 0; kx < 3; kx++) {
            uint32_t AD[2][2][2][4];   // [jbuf][term][mf][4]
            loadAfrag(A_, kx, 0, AD[0]);
            #pragma unroll
            for (int j = 0; j < 4; j++) {
                const int q   = (ky*3 + kx)*4 + j;
                const int cur = q & 1;
                const int jb  = j & 1;
                // prefetch next step's B-hi fragments
                loadBhi(q < 35 ? q + 1 : 35, Bhi[cur ^ 1]);
                // prefetch next j's A fragments (same kx)
                if (j < 3) loadAfrag(A_, kx, j + 1, AD[jb ^ 1]);
                // JIT-load this step's B-lo (consumed in pass 3)
                uint4 Bl[4];
                loadBlo(q, Bl);

                const uint32_t (*Ah)[4] = AD[jb][0];
                const uint32_t (*Al)[4] = AD[jb][1];
                const uint4* Bc = Bhi[cur];
                #pragma unroll
                for (int mf = 0; mf < 2; mf++)
                    #pragma unroll
                    for (int nf = 0; nf < 8; nf++) {
                        const uint4& f = Bc[nf >> 1];
                        mma_bf16(d[mf][nf], Ah[mf],
                                 (nf & 1) ? f.z : f.x, (nf & 1) ? f.w : f.y);
                    }
                #pragma unroll
                for (int mf = 0; mf < 2; mf++)
                    #pragma unroll
                    for (int nf = 0; nf < 8; nf++) {
                        const uint4& f = Bc[nf >> 1];
                        mma_bf16(d[mf][nf], Al[mf],
                                 (nf & 1) ? f.z : f.x, (nf & 1) ? f.w : f.y);
                    }
                #pragma unroll
                for (int mf = 0; mf < 2; mf++)
                    #pragma unroll
                    for (int nf = 0; nf < 8; nf++) {
                        const uint4& f = Bl[nf >> 1];
                        mma_bf16(d[mf][nf], Ah[mf],
                                 (nf & 1) ? f.z : f.x, (nf & 1) ? f.w : f.y);
                    }
            }
        }
    }

    // ---- epilogue ----
    #pragma unroll
    for (int mf = 0; mf < 2; mf++) {
        #pragma unroll
        for (int rr = 0; rr < 2; rr++) {
            const int p = wm*32 + mf*16 + (lane >> 2) + rr*8;
            const int w = w0 + p;
            const size_t nbase = ((size_t)((b*HH + h)*WW + w))*64;
            #pragma unroll
            for (int nf = 0; nf < 8; nf++) {
                const int cout = nf*8 + (lane & 3)*2;
                float v0 = d[mf][nf][rr*2 + 0];
                float v1 = d[mf][nf][rr*2 + 1];
                if (BNRELU) {
                    v0 = fmaxf(v0 * s_sc[cout]     + s_sh[cout],     0.f);
                    v1 = fmaxf(v1 * s_sc[cout + 1] + s_sh[cout + 1], 0.f);
                }
                if (SKIP) {
                    uint32_t sh2 = *(const uint32_t*)(sk_hi + nbase + cout);
                    uint32_t sl2 = *(const uint32_t*)(sk_lo + nbase + cout);
                    v0 += __bfloat162float(__ushort_as_bfloat16((unsigned short)(sh2 & 0xFFFF)))
                        + __bfloat162float(__ushort_as_bfloat16((unsigned short)(sl2 & 0xFFFF)));
                    v1 += __bfloat162float(__ushort_as_bfloat16((unsigned short)(sh2 >> 16)))
                        + __bfloat162float(__ushort_as_bfloat16((unsigned short)(sl2 >> 16)));
                }
                if (OUTF32) {
                    if (OSTRIDE == 64 || cout < OSTRIDE)
                        out_f32[((size_t)(b*OSTRIDE + cout)*HH + h)*WW + w] = v0;
                    if (OSTRIDE == 64 || cout + 1 < OSTRIDE)
                        out_f32[((size_t)(b*OSTRIDE + cout + 1)*HH + h)*WW + w] = v1;
                } else {
                    __nv_bfloat16 h0 = __float2bfloat16(v0);
                    __nv_bfloat16 h1 = __float2bfloat16(v1);
                    __nv_bfloat16 l0 = __float2bfloat16(v0 - __bfloat162float(h0));
                    __nv_bfloat16 l1 = __float2bfloat16(v1 - __bfloat162float(h1));
                    uint32_t ph = (uint32_t)__bfloat16_as_ushort(h0)
                                | ((uint32_t)__bfloat16_as_ushort(h1) << 16);
                    uint32_t pl = (uint32_t)__bfloat16_as_ushort(l0)
                                | ((uint32_t)__bfloat16_as_ushort(l1) << 16);
                    *(uint32_t*)(out_hi + nbase + cout) = ph;
                    *(uint32_t*)(out_lo + nbase + cout) = pl;
                }
            }
        }
    }
}

// ===========================================================================
// Adaptive filtering
// ===========================================================================
__global__ __launch_bounds__(256) void filt_h_kernel(
    const float* __restrict__ filt, const float* __restrict__ base,
    float* __restrict__ fh)
{
    int idx = blockIdx.x * 256 + threadIdx.x;
    int w  = idx & 511;
    int h  = (idx >> 9) & 511;
    int bc = idx >> 18;
    int ch = bc % 3;
    int b  = bc / 3;

    const float* lp = filt + ((size_t)(b*30 + ch*10)*HH + h)*WW + w;
    float l[5];
    #pragma unroll
    for (int i = 0; i < 5; i++) l[i] = lp[(size_t)i*HWSZ];
    float m = fmaxf(fmaxf(fmaxf(l[0], l[1]), fmaxf(l[2], l[3])), l[4]);
    float e[5], s = 0.f;
    #pragma unroll
    for (int i = 0; i < 5; i++) { e[i] = __expf(l[i] - m); s += e[i]; }
    float inv = 1.f / s;

    const float* bp = base + (size_t)bc*HWSZ + w;
    float r = 0.f;
    #pragma unroll
    for (int i = 0; i < 5; i++) {
        int hh2 = h - 2 + i;
        float bv = (hh2 >= 0 && hh2 < HH) ? bp[(size_t)hh2*WW] : 0.f;
        r += bv * e[i] * inv;
    }
    fh[idx] = r;
}

__global__ __launch_bounds__(256) void filt_w_kernel(
    const float* __restrict__ filt, const float* __restrict__ fh,
    float* __restrict__ out)
{
    int idx = blockIdx.x * 256 + threadIdx.x;
    int w  = idx & 511;
    int h  = (idx >> 9) & 511;
    int bc = idx >> 18;
    int ch = bc % 3;
    int b  = bc / 3;

    const float* lp = filt + ((size_t)(b*30 + ch*10 + 5)*HH + h)*WW + w;
    float l[5];
    #pragma unroll
    for (int i = 0; i < 5; i++) l[i] = lp[(size_t)i*HWSZ];
    float m = fmaxf(fmaxf(fmaxf(l[0], l[1]), fmaxf(l[2], l[3])), l[4]);
    float e[5], s = 0.f;
    #pragma unroll
    for (int i = 0; i < 5; i++) { e[i] = __expf(l[i] - m); s += e[i]; }
    float inv = 1.f / s;

    const float* fp = fh + ((size_t)bc*HH + h)*WW;
    float r = 0.f;
    #pragma unroll
    for (int i = 0; i < 5; i++) {
        int ww2 = w - 2 + i;
        float fv = (ww2 >= 0 && ww2 < WW) ? fp[ww2] : 0.f;
        r += fv * e[i] * inv;
    }
    out[idx] = r;
}

// ===========================================================================
extern "C" void kernel_launch(void* const* d_in, const int* in_sizes, int n_in,
                              void* d_out, int out_size)
{
    const float* fm     = (const float*)d_in[0];
    const float* base   = (const float*)d_in[1];
    const float* wfirst = (const float*)d_in[2];
    const float* kbw1   = (const float*)d_in[3];
    const float* kbg1   = (const float*)d_in[4];
    const float* kbb1   = (const float*)d_in[5];
    const float* kbm1   = (const float*)d_in[6];
    const float* kbv1   = (const float*)d_in[7];
    const float* kbw2   = (const float*)d_in[8];
    const float* kbg2   = (const float*)d_in[9];
    const float* kbb2   = (const float*)d_in[10];
    const float* kbm2   = (const float*)d_in[11];
    const float* kbv2   = (const float*)d_in[12];
    const float* wlast  = (const float*)d_in[13];
    float* out = (float*)d_out;

    float *F, *FHp;
    __nv_bfloat16 *P0h, *P0l, *P1h, *P1l, *P2h, *P2l;
    uint4* Fb;
    cudaGetSymbolAddress((void**)&F,   g_filt);
    cudaGetSymbolAddress((void**)&FHp, g_fh);
    cudaGetSymbolAddress((void**)&P0h, g_P0h);
    cudaGetSymbolAddress((void**)&P0l, g_P0l);
    cudaGetSymbolAddress((void**)&P1h, g_P1h);
    cudaGetSymbolAddress((void**)&P1l, g_P1l);
    cudaGetSymbolAddress((void**)&P2h, g_P2h);
    cudaGetSymbolAddress((void**)&P2l, g_P2l);
    cudaGetSymbolAddress((void**)&Fb,  g_FragB);

    cudaFuncSetAttribute(res_conv_kernel<true,false,false,64>,
                         cudaFuncAttributeMaxDynamicSharedMemorySize, RES_SMEM);
    cudaFuncSetAttribute(res_conv_kernel<true,true,false,64>,
                         cudaFuncAttributeMaxDynamicSharedMemorySize, RES_SMEM);
    cudaFuncSetAttribute(res_conv_kernel<false,false,true,30>,
                         cudaFuncAttributeMaxDynamicSharedMemorySize, RES_SMEM);

    // 1. weight prep -> mma-ready fragments (8 res convs + conv_last padded)
    prep_w_kernel<<<(9*9216 + 255)/256, 256>>>(kbw1, kbw2, wlast, Fb);

    // 2. conv_first -> P0 pair
    dim3 g7(WW/16, HH/8, BATCH);
    conv7x7_kernel<<<g7, 256>>>(fm, wfirst, P0h, P0l);

    // 3. residual blocks
    dim3 gr(WW/128, HH, BATCH);
    const size_t SL = 9216;   // uint4 stride per section
    __nv_bfloat16 *yh = P0h, *yl = P0l;
    __nv_bfloat16 *alt_h = P2h, *alt_l = P2l;
    for (int r = 0; r < 4; r++) {
        res_conv_kernel<true,false,false,64><<<gr, 128, RES_SMEM>>>(
            yh, yl, Fb + (size_t)(r*2+0)*SL,
            kbg1 + r*64, kbb1 + r*64, kbm1 + r*64, kbv1 + r*64,
            nullptr, nullptr, P1h, P1l, nullptr);
        res_conv_kernel<true,true,false,64><<<gr, 128, RES_SMEM>>>(
            P1h, P1l, Fb + (size_t)(r*2+1)*SL,
            kbg2 + r*64, kbb2 + r*64, kbm2 + r*64, kbv2 + r*64,
            yh, yl, alt_h, alt_l, nullptr);
        __nv_bfloat16* th = yh; __nv_bfloat16* tl = yl;
        yh = alt_h; yl = alt_l;
        alt_h = th; alt_l = tl;
    }

    // 4. conv_last via MMA (couts padded 30->64, stride-30 fp32 NCHW epilogue)
    res_conv_kernel<false,false,true,30><<<gr, 128, RES_SMEM>>>(
        yh, yl, Fb + (size_t)8*SL,
        nullptr, nullptr, nullptr, nullptr,
        nullptr, nullptr, nullptr, nullptr, F);

    // 5. adaptive filtering
    int npix = BATCH*3*HWSZ;
    filt_h_kernel<<<npix/256, 256>>>(F, base, FHp);
    filt_w_kernel<<<npix/256, 256>>>(F, FHp, out);
}